// round 1
// baseline (speedup 1.0000x reference)
#include <cuda_runtime.h>
#include <math.h>

// ---------------- problem constants ----------------
#define BB   2
#define SS   1024
#define DD   2048
#define HH   16
#define FF   8192
#define DHD  128
#define HALF 64
#define MM   (BB*SS)          // 2048 rows
#define KAUG (2*DHD)          // 256 augmented K dim

#define LAM   0.1f
#define HS    0.05f
#define BETA  0.3f
#define ALPHA 0.5f
#define CLIPV 10.0f
#define EPSV  1e-6f
#define SCALE 0.08838834764831845f   // 1/sqrt(128)
#define SQLAM 0.31622776601683794f   // sqrt(0.1)

// ---------------- static device scratch ----------------
static __device__ float g_xn  [MM*DD];
static __device__ float g_tmp [MM*DD];
static __device__ float g_tmp2[MM*DD];
static __device__ float g_cur [MM*DD];
static __device__ float g_h1  [MM*DD];
static __device__ float g_qa  [BB*HH*SS*KAUG];
static __device__ float g_ka  [BB*HH*SS*KAUG];
static __device__ float g_v   [BB*HH*SS*DHD];
static __device__ float g_ao  [BB*HH*SS*DHD];
static __device__ float g_sc  [(long long)BB*HH*SS*SS];
static __device__ float g_gt  [MM*FF];
static __device__ float g_up  [MM*FF];

// ---------------- GEMM: C = A[M,K] * op(B), op = B^T ([N,K]) or B ([K,N]) ----------------
// 128x128 tiles, BK=16, 256 threads, 8x8 register blocking. All dims must be
// multiples of (128,128,16) -- true for every GEMM in this problem.
template<bool BT>
__global__ void __launch_bounds__(256) gemm_k(
    const float* __restrict__ A, const float* __restrict__ B, float* __restrict__ C,
    int Mn, int Nn, int Kn, long long sA, long long sB, long long sC)
{
    constexpr int BK = 16;
    A += (long long)blockIdx.z * sA;
    B += (long long)blockIdx.z * sB;
    C += (long long)blockIdx.z * sC;

    __shared__ float As[BK][128];
    __shared__ float Bs[BK][128];

    const int tid = threadIdx.x;
    const int tr  = tid >> 4;     // 0..15
    const int tc  = tid & 15;     // 0..15
    const int rowBase = blockIdx.y * 128;
    const int colBase = blockIdx.x * 128;

    float acc[8][8];
#pragma unroll
    for (int i = 0; i < 8; i++)
#pragma unroll
        for (int j = 0; j < 8; j++) acc[i][j] = 0.f;

    for (int k0 = 0; k0 < Kn; k0 += BK) {
        // A tile: 128 rows x 16 k, row-major [M,K]
#pragma unroll
        for (int it = 0; it < 2; it++) {
            int idx = tid + it * 256;           // 0..511
            int r  = idx >> 2;                  // row in tile
            int kq = (idx & 3) << 2;            // k offset (float4)
            float4 v = *(const float4*)(A + (long long)(rowBase + r) * Kn + k0 + kq);
            As[kq+0][r] = v.x; As[kq+1][r] = v.y; As[kq+2][r] = v.z; As[kq+3][r] = v.w;
        }
        if (BT) {
            // B is [N,K]: same pattern as A
#pragma unroll
            for (int it = 0; it < 2; it++) {
                int idx = tid + it * 256;
                int r  = idx >> 2;
                int kq = (idx & 3) << 2;
                float4 v = *(const float4*)(B + (long long)(colBase + r) * Kn + k0 + kq);
                Bs[kq+0][r] = v.x; Bs[kq+1][r] = v.y; Bs[kq+2][r] = v.z; Bs[kq+3][r] = v.w;
            }
        } else {
            // B is [K,N]: 16 k-rows x 128 n-cols, coalesced along n
#pragma unroll
            for (int it = 0; it < 2; it++) {
                int idx = tid + it * 256;
                int kr = idx >> 5;              // 0..15
                int n  = (idx & 31) << 2;       // 0..124
                float4 v = *(const float4*)(B + (long long)(k0 + kr) * Nn + colBase + n);
                *(float4*)(&Bs[kr][n]) = v;
            }
        }
        __syncthreads();

#pragma unroll
        for (int k = 0; k < BK; k++) {
            float a[8], b[8];
            *(float4*)(a)   = *(const float4*)(&As[k][tr*8]);
            *(float4*)(a+4) = *(const float4*)(&As[k][tr*8+4]);
            *(float4*)(b)   = *(const float4*)(&Bs[k][tc*8]);
            *(float4*)(b+4) = *(const float4*)(&Bs[k][tc*8+4]);
#pragma unroll
            for (int i = 0; i < 8; i++)
#pragma unroll
                for (int j = 0; j < 8; j++)
                    acc[i][j] = fmaf(a[i], b[j], acc[i][j]);
        }
        __syncthreads();
    }

#pragma unroll
    for (int i = 0; i < 8; i++) {
        float* cp = C + (long long)(rowBase + tr*8 + i) * Nn + colBase + tc*8;
        *(float4*)(cp)   = make_float4(acc[i][0], acc[i][1], acc[i][2], acc[i][3]);
        *(float4*)(cp+4) = make_float4(acc[i][4], acc[i][5], acc[i][6], acc[i][7]);
    }
}

// ---------------- RMSNorm: one block per row of D=2048 ----------------
__global__ void rmsnorm_k(const float* __restrict__ x, const float* __restrict__ sc,
                          float* __restrict__ o)
{
    const int row = blockIdx.x;
    const float* xr = x + (long long)row * DD;
    float*       orw = o + (long long)row * DD;
    float s = 0.f;
    for (int j = threadIdx.x; j < DD; j += 256) { float v = xr[j]; s += v * v; }
    __shared__ float red[256];
    red[threadIdx.x] = s; __syncthreads();
    for (int t = 128; t > 0; t >>= 1) {
        if (threadIdx.x < t) red[threadIdx.x] += red[threadIdx.x + t];
        __syncthreads();
    }
    float r = rsqrtf(red[0] * (1.0f / DD) + EPSV);
    for (int j = threadIdx.x; j < DD; j += 256) orw[j] = xr[j] * r * sc[j];
}

// ---------------- RoPE + augmentation: [M,D]=(b,s,h,dh) -> [b,h,s,256] ----------------
__global__ void rope_aug_k(const float* __restrict__ in, float* __restrict__ out)
{
    int idx = blockIdx.x * 256 + threadIdx.x;     // B*S*H*HALF = 2^21 threads
    int d = idx & 63;
    int h = (idx >> 6) & 15;
    int s = (idx >> 10) & 1023;
    int b = idx >> 20;
    long long m = (long long)b * SS + s;
    float q1 = in[m * DD + h * DHD + d];
    float q2 = in[m * DD + h * DHD + HALF + d];
    float inv = expf(-(float)d * (9.210340371976184f / 64.0f)); // 10000^(-d/64)
    float ang = (float)s * inv;
    float cs, sn; sincosf(ang, &sn, &cs);
    float o1 = q1 * cs - q2 * sn;
    float o2 = q1 * sn + q2 * cs;
    long long base = (((long long)(b * HH + h)) * SS + s) * KAUG;
    out[base + d]              = o1;
    out[base + HALF + d]       = o2;
    out[base + DHD + d]        = SQLAM * o1 * o1;
    out[base + DHD + HALF + d] = SQLAM * o2 * o2;
}

// ---------------- V transpose: [M,D]=(b,s,h,d) -> [b,h,s,d] ----------------
__global__ void transpose_v_k(const float* __restrict__ in, float* __restrict__ out)
{
    int idx = blockIdx.x * 256 + threadIdx.x;     // M*D threads
    int d = idx & 127;
    int h = (idx >> 7) & 15;
    int m = idx >> 11;
    int b = m >> 10, s = m & 1023;
    out[(((long long)(b * HH + h)) * SS + s) * DHD + d] = in[idx];
}

// ---------------- causal softmax (in place), scale applied here ----------------
__global__ void softmax_k(float* __restrict__ sc)
{
    long long row = blockIdx.x;                   // B*H*S rows
    int i = (int)(row % SS);                      // query position
    float* p = sc + row * SS;
    int tid = threadIdx.x;
    __shared__ float red[256];

    float m = -1e30f;
    for (int j = tid; j <= i; j += 256) m = fmaxf(m, p[j] * SCALE);
    red[tid] = m; __syncthreads();
    for (int t = 128; t > 0; t >>= 1) {
        if (tid < t) red[tid] = fmaxf(red[tid], red[tid + t]);
        __syncthreads();
    }
    m = red[0]; __syncthreads();

    float sum = 0.f;
    for (int j = tid; j <= i; j += 256) {
        float e = expf(p[j] * SCALE - m);
        p[j] = e; sum += e;
    }
    red[tid] = sum; __syncthreads();
    for (int t = 128; t > 0; t >>= 1) {
        if (tid < t) red[tid] += red[tid + t];
        __syncthreads();
    }
    float inv = 1.f / red[0];

    for (int j = tid; j < SS; j += 256) p[j] = (j <= i) ? p[j] * inv : 0.f;
}

// ---------------- hadamard mix (dh roll) + transpose [b,h,s,d] -> [M,D] ----------------
__global__ void mix_transpose_k(const float* __restrict__ ao, float* __restrict__ out)
{
    int idx = blockIdx.x * 256 + threadIdx.x;     // B*H*S*DH threads
    int d  = idx & 127;
    int s  = (idx >> 7) & 1023;
    int bh = idx >> 17;
    int h = bh & 15, b = bh >> 4;
    float v  = ao[idx];
    float pv = ao[(idx - d) | ((d + 127) & 127)];
    out[((long long)(b * SS + s)) * DD + h * DHD + d] = v * (1.f + HS * pv);
}

// ---------------- elementwise kernels ----------------
__global__ void copy_k(float* __restrict__ dst, const float* __restrict__ src, int n)
{ int i = blockIdx.x * 256 + threadIdx.x; if (i < n) dst[i] = src[i]; }

__global__ void add_k(float* __restrict__ dst, const float* __restrict__ src, int n)
{ int i = blockIdx.x * 256 + threadIdx.x; if (i < n) dst[i] += src[i]; }

__global__ void silu_mul_k(float* __restrict__ g, const float* __restrict__ u, int n)
{
    int i = blockIdx.x * 256 + threadIdx.x;
    if (i < n) { float x = g[i]; g[i] = (x / (1.f + expf(-x))) * u[i]; }
}

// hidden mix along F (reads g, writes o)
__global__ void mix_row_k(const float* __restrict__ g, float* __restrict__ o)
{
    int i = blockIdx.x * 256 + threadIdx.x;       // M*F threads
    int col  = i & (FF - 1);
    int prev = (i - col) | ((col + FF - 1) & (FF - 1));
    float v = g[i];
    o[i] = v * (1.f + HS * g[prev]);
}

__global__ void x2_k(float* __restrict__ cur, const float* __restrict__ h1,
                     const float* __restrict__ x, int n)
{ int i = blockIdx.x * 256 + threadIdx.x; if (i < n) cur[i] = (1.f + BETA) * h1[i] - BETA * x[i]; }

__global__ void final_k(float* __restrict__ out, const float* __restrict__ h1,
                        const float* __restrict__ h2, int n)
{
    int i = blockIdx.x * 256 + threadIdx.x;
    if (i < n) {
        float v = ALPHA * h1[i] + (1.f - ALPHA) * h2[i];
        out[i] = fminf(fmaxf(v, -CLIPV), CLIPV);
    }
}

// ---------------- host orchestration ----------------
static void run_pass(const float* Wq, const float* Wk, const float* Wv, const float* Wo,
                     const float* Wg, const float* Wu, const float* Wd,
                     const float* na, const float* nb,
                     float* cur, float* xn, float* tmp, float* tmp2,
                     float* qa, float* ka, float* v, float* ao, float* sc,
                     float* gt, float* up)
{
    const int nMD = MM * DD, nMF = MM * FF;
    const dim3 gDD(DD/128, MM/128, 1);
    const dim3 gFF(FF/128, MM/128, 1);

    rmsnorm_k<<<MM, 256>>>(cur, na, xn);

    gemm_k<true><<<gDD, 256>>>(xn, Wq, tmp, MM, DD, DD, 0, 0, 0);
    rope_aug_k<<<(BB*SS*HH*HALF)/256, 256>>>(tmp, qa);
    gemm_k<true><<<gDD, 256>>>(xn, Wk, tmp, MM, DD, DD, 0, 0, 0);
    rope_aug_k<<<(BB*SS*HH*HALF)/256, 256>>>(tmp, ka);
    gemm_k<true><<<gDD, 256>>>(xn, Wv, tmp, MM, DD, DD, 0, 0, 0);
    transpose_v_k<<<nMD/256, 256>>>(tmp, v);

    // scores: per-head GEMM  [S x S] = Qaug[S x 256] * Kaug^T
    gemm_k<true><<<dim3(SS/128, SS/128, BB*HH), 256>>>(
        qa, ka, sc, SS, SS, KAUG,
        (long long)SS*KAUG, (long long)SS*KAUG, (long long)SS*SS);
    softmax_k<<<BB*HH*SS, 256>>>(sc);
    // O = P * V  per head
    gemm_k<false><<<dim3(DHD/128, SS/128, BB*HH), 256>>>(
        sc, v, ao, SS, DHD, SS,
        (long long)SS*SS, (long long)SS*DHD, (long long)SS*DHD);

    mix_transpose_k<<<nMD/256, 256>>>(ao, tmp);
    gemm_k<true><<<gDD, 256>>>(tmp, Wo, tmp2, MM, DD, DD, 0, 0, 0);
    add_k<<<(nMD+255)/256, 256>>>(cur, tmp2, nMD);

    rmsnorm_k<<<MM, 256>>>(cur, nb, xn);
    gemm_k<true><<<gFF, 256>>>(xn, Wg, gt, MM, FF, DD, 0, 0, 0);
    gemm_k<true><<<gFF, 256>>>(xn, Wu, up, MM, FF, DD, 0, 0, 0);
    silu_mul_k<<<(nMF+255)/256, 256>>>(gt, up, nMF);
    mix_row_k<<<nMF/256, 256>>>(gt, up);
    gemm_k<true><<<gDD, 256>>>(up, Wd, tmp, MM, DD, FF, 0, 0, 0);
    add_k<<<(nMD+255)/256, 256>>>(cur, tmp, nMD);
}

extern "C" void kernel_launch(void* const* d_in, const int* in_sizes, int n_in,
                              void* d_out, int out_size)
{
    (void)in_sizes; (void)n_in; (void)out_size;
    const float* x  = (const float*)d_in[0];
    const float* Wq = (const float*)d_in[1];
    const float* Wk = (const float*)d_in[2];
    const float* Wv = (const float*)d_in[3];
    const float* Wo = (const float*)d_in[4];
    // d_in[5] = gate_w: provably unused (rotate_half invariance => o2 == o1)
    const float* n1 = (const float*)d_in[6];
    const float* n2 = (const float*)d_in[7];
    const float* n3 = (const float*)d_in[8];
    const float* n4 = (const float*)d_in[9];
    const float* Wg = (const float*)d_in[10];
    const float* Wu = (const float*)d_in[11];
    const float* Wd = (const float*)d_in[12];
    float* out = (float*)d_out;

    float *xn, *tmp, *tmp2, *cur, *h1, *qa, *ka, *v, *ao, *sc, *gt, *up;
    cudaGetSymbolAddress((void**)&xn,  g_xn);
    cudaGetSymbolAddress((void**)&tmp, g_tmp);
    cudaGetSymbolAddress((void**)&tmp2,g_tmp2);
    cudaGetSymbolAddress((void**)&cur, g_cur);
    cudaGetSymbolAddress((void**)&h1,  g_h1);
    cudaGetSymbolAddress((void**)&qa,  g_qa);
    cudaGetSymbolAddress((void**)&ka,  g_ka);
    cudaGetSymbolAddress((void**)&v,   g_v);
    cudaGetSymbolAddress((void**)&ao,  g_ao);
    cudaGetSymbolAddress((void**)&sc,  g_sc);
    cudaGetSymbolAddress((void**)&gt,  g_gt);
    cudaGetSymbolAddress((void**)&up,  g_up);

    const int nMD = MM * DD;

    // pass 1
    copy_k<<<(nMD+255)/256, 256>>>(cur, x, nMD);
    run_pass(Wq, Wk, Wv, Wo, Wg, Wu, Wd, n1, n2,
             cur, xn, tmp, tmp2, qa, ka, v, ao, sc, gt, up);
    copy_k<<<(nMD+255)/256, 256>>>(h1, cur, nMD);

    // x2 = h1 + beta*(h1 - x)
    x2_k<<<(nMD+255)/256, 256>>>(cur, h1, x, nMD);

    // pass 2
    run_pass(Wq, Wk, Wv, Wo, Wg, Wu, Wd, n3, n4,
             cur, xn, tmp, tmp2, qa, ka, v, ao, sc, gt, up);

    // out = clip(alpha*h1 + (1-alpha)*h2)
    final_k<<<(nMD+255)/256, 256>>>(out, h1, cur, nMD);
}

// round 2
// speedup vs baseline: 1.9509x; 1.9509x over previous
#include <cuda_runtime.h>
#include <math.h>

// ---------------- problem constants ----------------
#define BB   2
#define SS   1024
#define DD   2048
#define HH   16
#define FF   8192
#define DHD  128
#define HALF 64
#define MM   (BB*SS)          // 2048 rows
#define KAUG (2*DHD)          // 256 augmented K dim

#define LAM   0.1f
#define HS    0.05f
#define BETA  0.3f
#define ALPHA 0.5f
#define CLIPV 10.0f
#define EPSV  1e-6f
#define SCALE 0.08838834764831845f   // 1/sqrt(128)
#define SQLAM 0.31622776601683794f   // sqrt(0.1)

// ---------------- static device scratch ----------------
static __device__ float g_xn  [MM*DD];
static __device__ float g_tmp [MM*DD];
static __device__ float g_cur [MM*DD];
static __device__ float g_h1  [MM*DD];
static __device__ float g_qa  [BB*HH*SS*KAUG];
static __device__ float g_ka  [BB*HH*SS*KAUG];
static __device__ float g_v   [BB*HH*SS*DHD];
static __device__ float g_ao  [BB*HH*SS*DHD];
static __device__ float g_sc  [(long long)BB*HH*SS*SS];
static __device__ float g_gt  [MM*FF];
static __device__ float g_up  [MM*FF];

// ---------------- tf32 helpers ----------------
__device__ __forceinline__ unsigned f2tf(float f) {
    unsigned u;
    asm("cvt.rna.tf32.f32 %0, %1;" : "=r"(u) : "f"(f));
    return u;
}

__device__ __forceinline__ void mma_tf32(float* c, const unsigned* a, const unsigned* b) {
    asm volatile(
        "mma.sync.aligned.m16n8k8.row.col.f32.tf32.tf32.f32 "
        "{%0,%1,%2,%3}, {%4,%5,%6,%7}, {%8,%9}, {%0,%1,%2,%3};\n"
        : "+f"(c[0]), "+f"(c[1]), "+f"(c[2]), "+f"(c[3])
        : "r"(a[0]), "r"(a[1]), "r"(a[2]), "r"(a[3]),
          "r"(b[0]), "r"(b[1]));
}

// ---------------- TF32 tensor-core GEMM ----------------
// C[M,N] = A[M,K] * op(B), op: BT -> B is [N,K]; !BT -> B is [K,N].
// ADD: C += result (fused residual add).
// Tiles: BM=128, BN=128, BK=32. 256 threads = 8 warps (4m x 2n), warp tile 32x64.
// All problem dims are multiples of (128,128,32).
template<bool BT, bool ADD>
__global__ void __launch_bounds__(256) gemm_tc(
    const float* __restrict__ A, const float* __restrict__ B, float* __restrict__ C,
    int Mn, int Nn, int Kn, long long sA, long long sB, long long sC)
{
    A += (long long)blockIdx.z * sA;
    B += (long long)blockIdx.z * sB;
    C += (long long)blockIdx.z * sC;

    // [k][m] / [k][n], padded stride 132 (528B, 16B-aligned rows)
    __shared__ __align__(16) unsigned As[32][132];
    __shared__ __align__(16) unsigned Bs[32][132];

    const int tid  = threadIdx.x;
    const int warp = tid >> 5, lane = tid & 31;
    const int gid  = lane >> 2, tig = lane & 3;
    const int wm   = (warp & 3) * 32;
    const int wn   = (warp >> 2) * 64;
    const int rowBase = blockIdx.y * 128;
    const int colBase = blockIdx.x * 128;

    float acc[2][8][4];
#pragma unroll
    for (int mt = 0; mt < 2; mt++)
#pragma unroll
        for (int nt = 0; nt < 8; nt++)
#pragma unroll
            for (int j = 0; j < 4; j++) acc[mt][nt][j] = 0.f;

    // --- load addressing ---
    // A (and BT-B): 128 rows x 32 k = 1024 float4 along k; 4 per thread.
    const int m0  = tid >> 3;            // 0..31, row = m0 + it*32
    const int kqA = (tid & 7) << 2;      // k offset of float4
    // BN-B: 32 k x 128 n = 1024 float4 along n; 4 per thread.
    const int k0B = tid >> 5;            // 0..7, k = k0B + it*8
    const int nqB = (tid & 31) << 2;     // n offset of float4

    float4 ra[4], rb[4];

    // prefetch tile 0
#pragma unroll
    for (int it = 0; it < 4; it++) {
        int m = m0 + it * 32;
        ra[it] = *(const float4*)(A + (long long)(rowBase + m) * Kn + kqA);
    }
    if (BT) {
#pragma unroll
        for (int it = 0; it < 4; it++) {
            int n = m0 + it * 32;
            rb[it] = *(const float4*)(B + (long long)(colBase + n) * Kn + kqA);
        }
    } else {
#pragma unroll
        for (int it = 0; it < 4; it++) {
            int k = k0B + it * 8;
            rb[it] = *(const float4*)(B + (long long)k * Nn + colBase + nqB);
        }
    }

    const int iters = Kn >> 5;
    for (int t = 0; t < iters; t++) {
        // stage registers -> shared (with tf32 rounding)
#pragma unroll
        for (int it = 0; it < 4; it++) {
            int m = m0 + it * 32;
            As[kqA + 0][m] = f2tf(ra[it].x);
            As[kqA + 1][m] = f2tf(ra[it].y);
            As[kqA + 2][m] = f2tf(ra[it].z);
            As[kqA + 3][m] = f2tf(ra[it].w);
        }
        if (BT) {
#pragma unroll
            for (int it = 0; it < 4; it++) {
                int n = m0 + it * 32;
                Bs[kqA + 0][n] = f2tf(rb[it].x);
                Bs[kqA + 1][n] = f2tf(rb[it].y);
                Bs[kqA + 2][n] = f2tf(rb[it].z);
                Bs[kqA + 3][n] = f2tf(rb[it].w);
            }
        } else {
#pragma unroll
            for (int it = 0; it < 4; it++) {
                int k = k0B + it * 8;
                uint4 u;
                u.x = f2tf(rb[it].x); u.y = f2tf(rb[it].y);
                u.z = f2tf(rb[it].z); u.w = f2tf(rb[it].w);
                *(uint4*)(&Bs[k][nqB]) = u;
            }
        }
        __syncthreads();

        // prefetch next tile while computing
        if (t + 1 < iters) {
            int koff = (t + 1) << 5;
#pragma unroll
            for (int it = 0; it < 4; it++) {
                int m = m0 + it * 32;
                ra[it] = *(const float4*)(A + (long long)(rowBase + m) * Kn + koff + kqA);
            }
            if (BT) {
#pragma unroll
                for (int it = 0; it < 4; it++) {
                    int n = m0 + it * 32;
                    rb[it] = *(const float4*)(B + (long long)(colBase + n) * Kn + koff + kqA);
                }
            } else {
#pragma unroll
                for (int it = 0; it < 4; it++) {
                    int k = k0B + it * 8;
                    rb[it] = *(const float4*)(B + (long long)(koff + k) * Nn + colBase + nqB);
                }
            }
        }

        // compute: 4 k-steps of 8
#pragma unroll
        for (int kk = 0; kk < 4; kk++) {
            const int kb = kk * 8;
            unsigned a[2][4], b[8][2];
#pragma unroll
            for (int mt = 0; mt < 2; mt++) {
                int mr = wm + mt * 16 + gid;
                a[mt][0] = As[kb + tig][mr];
                a[mt][1] = As[kb + tig][mr + 8];
                a[mt][2] = As[kb + tig + 4][mr];
                a[mt][3] = As[kb + tig + 4][mr + 8];
            }
#pragma unroll
            for (int nt = 0; nt < 8; nt++) {
                int nc = wn + nt * 8 + gid;
                b[nt][0] = Bs[kb + tig][nc];
                b[nt][1] = Bs[kb + tig + 4][nc];
            }
#pragma unroll
            for (int mt = 0; mt < 2; mt++)
#pragma unroll
                for (int nt = 0; nt < 8; nt++)
                    mma_tf32(acc[mt][nt], a[mt], b[nt]);
        }
        __syncthreads();
    }

    // epilogue
#pragma unroll
    for (int mt = 0; mt < 2; mt++) {
        int r0 = rowBase + wm + mt * 16 + gid;
#pragma unroll
        for (int nt = 0; nt < 8; nt++) {
            int c = colBase + wn + nt * 8 + 2 * tig;
            float* p0 = C + (long long)r0 * Nn + c;
            float* p1 = p0 + 8 * (long long)Nn;
            if (ADD) {
                p0[0] += acc[mt][nt][0]; p0[1] += acc[mt][nt][1];
                p1[0] += acc[mt][nt][2]; p1[1] += acc[mt][nt][3];
            } else {
                p0[0] = acc[mt][nt][0]; p0[1] = acc[mt][nt][1];
                p1[0] = acc[mt][nt][2]; p1[1] = acc[mt][nt][3];
            }
        }
    }
}

// ---------------- RMSNorm: one block per row of D=2048 ----------------
__global__ void rmsnorm_k(const float* __restrict__ x, const float* __restrict__ sc,
                          float* __restrict__ o)
{
    const int row = blockIdx.x;
    const float* xr = x + (long long)row * DD;
    float*       orw = o + (long long)row * DD;
    float s = 0.f;
    for (int j = threadIdx.x; j < DD; j += 256) { float v = xr[j]; s += v * v; }
    __shared__ float red[256];
    red[threadIdx.x] = s; __syncthreads();
    for (int t = 128; t > 0; t >>= 1) {
        if (threadIdx.x < t) red[threadIdx.x] += red[threadIdx.x + t];
        __syncthreads();
    }
    float r = rsqrtf(red[0] * (1.0f / DD) + EPSV);
    for (int j = threadIdx.x; j < DD; j += 256) orw[j] = xr[j] * r * sc[j];
}

// ---------------- RoPE + augmentation: [M,D]=(b,s,h,dh) -> [b,h,s,256] ----------------
__global__ void rope_aug_k(const float* __restrict__ in, float* __restrict__ out)
{
    int idx = blockIdx.x * 256 + threadIdx.x;     // B*S*H*HALF threads
    int d = idx & 63;
    int h = (idx >> 6) & 15;
    int s = (idx >> 10) & 1023;
    int b = idx >> 20;
    long long m = (long long)b * SS + s;
    float q1 = in[m * DD + h * DHD + d];
    float q2 = in[m * DD + h * DHD + HALF + d];
    float inv = expf(-(float)d * (9.210340371976184f / 64.0f)); // 10000^(-d/64)
    float ang = (float)s * inv;
    float cs, sn; sincosf(ang, &sn, &cs);
    float o1 = q1 * cs - q2 * sn;
    float o2 = q1 * sn + q2 * cs;
    long long base = (((long long)(b * HH + h)) * SS + s) * KAUG;
    out[base + d]              = o1;
    out[base + HALF + d]       = o2;
    out[base + DHD + d]        = SQLAM * o1 * o1;
    out[base + DHD + HALF + d] = SQLAM * o2 * o2;
}

// ---------------- V transpose: [M,D]=(b,s,h,d) -> [b,h,s,d] ----------------
__global__ void transpose_v_k(const float* __restrict__ in, float* __restrict__ out)
{
    int idx = blockIdx.x * 256 + threadIdx.x;     // M*D threads
    int d = idx & 127;
    int h = (idx >> 7) & 15;
    int m = idx >> 11;
    int b = m >> 10, s = m & 1023;
    out[(((long long)(b * HH + h)) * SS + s) * DHD + d] = in[idx];
}

// ---------------- causal softmax (in place), scale applied here ----------------
__global__ void softmax_k(float* __restrict__ sc)
{
    long long row = blockIdx.x;                   // B*H*S rows
    int i = (int)(row % SS);                      // query position
    float* p = sc + row * SS;
    int tid = threadIdx.x;
    __shared__ float red[256];

    float m = -1e30f;
    for (int j = tid; j <= i; j += 256) m = fmaxf(m, p[j] * SCALE);
    red[tid] = m; __syncthreads();
    for (int t = 128; t > 0; t >>= 1) {
        if (tid < t) red[tid] = fmaxf(red[tid], red[tid + t]);
        __syncthreads();
    }
    m = red[0]; __syncthreads();

    float sum = 0.f;
    for (int j = tid; j <= i; j += 256) {
        float e = expf(p[j] * SCALE - m);
        p[j] = e; sum += e;
    }
    red[tid] = sum; __syncthreads();
    for (int t = 128; t > 0; t >>= 1) {
        if (tid < t) red[tid] += red[tid + t];
        __syncthreads();
    }
    float inv = 1.f / red[0];

    for (int j = tid; j < SS; j += 256) p[j] = (j <= i) ? p[j] * inv : 0.f;
}

// ---------------- hadamard mix (dh roll) + transpose [b,h,s,d] -> [M,D] ----------------
__global__ void mix_transpose_k(const float* __restrict__ ao, float* __restrict__ out)
{
    int idx = blockIdx.x * 256 + threadIdx.x;     // B*H*S*DH threads
    int d  = idx & 127;
    int s  = (idx >> 7) & 1023;
    int bh = idx >> 17;
    int h = bh & 15, b = bh >> 4;
    float v  = ao[idx];
    float pv = ao[(idx - d) | ((d + 127) & 127)];
    out[((long long)(b * SS + s)) * DD + h * DHD + d] = v * (1.f + HS * pv);
}

// ---------------- elementwise kernels ----------------
__global__ void copy_k(float* __restrict__ dst, const float* __restrict__ src, int n)
{ int i = blockIdx.x * 256 + threadIdx.x; if (i < n) dst[i] = src[i]; }

__global__ void silu_mul_k(float* __restrict__ g, const float* __restrict__ u, int n)
{
    int i = blockIdx.x * 256 + threadIdx.x;
    if (i < n) { float x = g[i]; g[i] = (x / (1.f + expf(-x))) * u[i]; }
}

// hidden mix along F (reads g, writes o)
__global__ void mix_row_k(const float* __restrict__ g, float* __restrict__ o)
{
    int i = blockIdx.x * 256 + threadIdx.x;       // M*F threads
    int col  = i & (FF - 1);
    int prev = (i - col) | ((col + FF - 1) & (FF - 1));
    float v = g[i];
    o[i] = v * (1.f + HS * g[prev]);
}

__global__ void x2_k(float* __restrict__ cur, const float* __restrict__ h1,
                     const float* __restrict__ x, int n)
{ int i = blockIdx.x * 256 + threadIdx.x; if (i < n) cur[i] = (1.f + BETA) * h1[i] - BETA * x[i]; }

__global__ void final_k(float* __restrict__ out, const float* __restrict__ h1,
                        const float* __restrict__ h2, int n)
{
    int i = blockIdx.x * 256 + threadIdx.x;
    if (i < n) {
        float v = ALPHA * h1[i] + (1.f - ALPHA) * h2[i];
        out[i] = fminf(fmaxf(v, -CLIPV), CLIPV);
    }
}

// ---------------- host orchestration ----------------
static void run_pass(const float* Wq, const float* Wk, const float* Wv, const float* Wo,
                     const float* Wg, const float* Wu, const float* Wd,
                     const float* na, const float* nb,
                     float* cur, float* xn, float* tmp,
                     float* qa, float* ka, float* v, float* ao, float* sc,
                     float* gt, float* up)
{
    const int nMD = MM * DD, nMF = MM * FF;
    const dim3 gDD(DD/128, MM/128, 1);
    const dim3 gFF(FF/128, MM/128, 1);

    rmsnorm_k<<<MM, 256>>>(cur, na, xn);

    gemm_tc<true, false><<<gDD, 256>>>(xn, Wq, tmp, MM, DD, DD, 0, 0, 0);
    rope_aug_k<<<(BB*SS*HH*HALF)/256, 256>>>(tmp, qa);
    gemm_tc<true, false><<<gDD, 256>>>(xn, Wk, tmp, MM, DD, DD, 0, 0, 0);
    rope_aug_k<<<(BB*SS*HH*HALF)/256, 256>>>(tmp, ka);
    gemm_tc<true, false><<<gDD, 256>>>(xn, Wv, tmp, MM, DD, DD, 0, 0, 0);
    transpose_v_k<<<nMD/256, 256>>>(tmp, v);

    // scores: per-head GEMM  [S x S] = Qaug[S x 256] * Kaug^T
    gemm_tc<true, false><<<dim3(SS/128, SS/128, BB*HH), 256>>>(
        qa, ka, sc, SS, SS, KAUG,
        (long long)SS*KAUG, (long long)SS*KAUG, (long long)SS*SS);
    softmax_k<<<BB*HH*SS, 256>>>(sc);
    // O = P * V  per head
    gemm_tc<false, false><<<dim3(DHD/128, SS/128, BB*HH), 256>>>(
        sc, v, ao, SS, DHD, SS,
        (long long)SS*SS, (long long)SS*DHD, (long long)SS*DHD);

    mix_transpose_k<<<nMD/256, 256>>>(ao, tmp);
    // fused residual: cur += mix(attn_out) @ Wo^T
    gemm_tc<true, true><<<gDD, 256>>>(tmp, Wo, cur, MM, DD, DD, 0, 0, 0);

    rmsnorm_k<<<MM, 256>>>(cur, nb, xn);
    gemm_tc<true, false><<<gFF, 256>>>(xn, Wg, gt, MM, FF, DD, 0, 0, 0);
    gemm_tc<true, false><<<gFF, 256>>>(xn, Wu, up, MM, FF, DD, 0, 0, 0);
    silu_mul_k<<<(nMF+255)/256, 256>>>(gt, up, nMF);
    mix_row_k<<<nMF/256, 256>>>(gt, up);
    // fused residual: cur += hidden @ Wd^T
    gemm_tc<true, true><<<gDD, 256>>>(up, Wd, cur, MM, DD, FF, 0, 0, 0);
}

extern "C" void kernel_launch(void* const* d_in, const int* in_sizes, int n_in,
                              void* d_out, int out_size)
{
    (void)in_sizes; (void)n_in; (void)out_size;
    const float* x  = (const float*)d_in[0];
    const float* Wq = (const float*)d_in[1];
    const float* Wk = (const float*)d_in[2];
    const float* Wv = (const float*)d_in[3];
    const float* Wo = (const float*)d_in[4];
    // d_in[5] = gate_w: unused (rotate_half invariance => o2 == o1)
    const float* n1 = (const float*)d_in[6];
    const float* n2 = (const float*)d_in[7];
    const float* n3 = (const float*)d_in[8];
    const float* n4 = (const float*)d_in[9];
    const float* Wg = (const float*)d_in[10];
    const float* Wu = (const float*)d_in[11];
    const float* Wd = (const float*)d_in[12];
    float* out = (float*)d_out;

    float *xn, *tmp, *cur, *h1, *qa, *ka, *v, *ao, *sc, *gt, *up;
    cudaGetSymbolAddress((void**)&xn,  g_xn);
    cudaGetSymbolAddress((void**)&tmp, g_tmp);
    cudaGetSymbolAddress((void**)&cur, g_cur);
    cudaGetSymbolAddress((void**)&h1,  g_h1);
    cudaGetSymbolAddress((void**)&qa,  g_qa);
    cudaGetSymbolAddress((void**)&ka,  g_ka);
    cudaGetSymbolAddress((void**)&v,   g_v);
    cudaGetSymbolAddress((void**)&ao,  g_ao);
    cudaGetSymbolAddress((void**)&sc,  g_sc);
    cudaGetSymbolAddress((void**)&gt,  g_gt);
    cudaGetSymbolAddress((void**)&up,  g_up);

    const int nMD = MM * DD;

    // pass 1
    copy_k<<<(nMD+255)/256, 256>>>(cur, x, nMD);
    run_pass(Wq, Wk, Wv, Wo, Wg, Wu, Wd, n1, n2,
             cur, xn, tmp, qa, ka, v, ao, sc, gt, up);
    copy_k<<<(nMD+255)/256, 256>>>(h1, cur, nMD);

    // x2 = h1 + beta*(h1 - x)
    x2_k<<<(nMD+255)/256, 256>>>(cur, h1, x, nMD);

    // pass 2
    run_pass(Wq, Wk, Wv, Wo, Wg, Wu, Wd, n3, n4,
             cur, xn, tmp, qa, ka, v, ao, sc, gt, up);

    // out = clip(alpha*h1 + (1-alpha)*h2)
    final_k<<<(nMD+255)/256, 256>>>(out, h1, cur, nMD);
}

// round 4
// speedup vs baseline: 2.8174x; 1.4441x over previous
#include <cuda_runtime.h>
#include <math.h>
#include <stdint.h>

// ---------------- problem constants ----------------
#define BB   2
#define SS   1024
#define DD   2048
#define HH   16
#define FF   8192
#define DHD  128
#define HALF 64
#define MM   (BB*SS)          // 2048 rows
#define KAUG (2*DHD)          // 256 augmented K dim

#define HS    0.05f
#define BETA  0.3f
#define ALPHA 0.5f
#define CLIPV 10.0f
#define EPSV  1e-6f
#define SCALE 0.08838834764831845f   // 1/sqrt(128)
#define SQLAM 0.31622776601683794f   // sqrt(0.1)

// ---------------- static device scratch ----------------
static __device__ __align__(128) float g_xn  [MM*DD];
static __device__ __align__(128) float g_tmp [MM*DD];
static __device__ __align__(128) float g_cur [MM*DD];
static __device__ __align__(128) float g_h1  [MM*DD];
static __device__ __align__(128) float g_qa  [BB*HH*SS*KAUG];
static __device__ __align__(128) float g_ka  [BB*HH*SS*KAUG];
static __device__ __align__(128) float g_vt  [BB*HH*SS*DHD];
static __device__ __align__(128) float g_ao  [BB*HH*SS*DHD];
static __device__ __align__(128) float g_sc  [(long long)BB*HH*SS*SS];
static __device__ __align__(128) float g_gt  [MM*FF];
static __device__ __align__(128) float g_up  [MM*FF];
// tf32-rounded weights
static __device__ __align__(128) float g_wq[DD*DD], g_wk[DD*DD], g_wv[DD*DD], g_wo[DD*DD];
static __device__ __align__(128) float g_wg[FF*DD], g_wu[FF*DD], g_wd[DD*FF];

// ---------------- helpers ----------------
__device__ __forceinline__ unsigned f2tf(float f) {
    unsigned u;
    asm("cvt.rna.tf32.f32 %0, %1;" : "=r"(u) : "f"(f));
    return u;
}
__device__ __forceinline__ float f2tf_f(float f) { unsigned u = f2tf(f); return __uint_as_float(u); }

__device__ __forceinline__ uint32_t smem_u32(const void* p) {
    uint32_t a;
    asm("{ .reg .u64 t; cvta.to.shared.u64 t, %1; cvt.u32.u64 %0, t; }" : "=r"(a) : "l"(p));
    return a;
}
__device__ __forceinline__ void cpasync16(uint32_t dst, const float* src) {
    asm volatile("cp.async.cg.shared.global [%0], [%1], 16;" :: "r"(dst), "l"(src));
}
#define CP_COMMIT()  asm volatile("cp.async.commit_group;" ::: "memory")
#define CP_WAIT1()   asm volatile("cp.async.wait_group 1;" ::: "memory")
#define CP_WAIT0()   asm volatile("cp.async.wait_group 0;" ::: "memory")

__device__ __forceinline__ void mma_tf32(float* c, const unsigned* a, const unsigned* b) {
    asm volatile(
        "mma.sync.aligned.m16n8k8.row.col.f32.tf32.tf32.f32 "
        "{%0,%1,%2,%3}, {%4,%5,%6,%7}, {%8,%9}, {%0,%1,%2,%3};\n"
        : "+f"(c[0]), "+f"(c[1]), "+f"(c[2]), "+f"(c[3])
        : "r"(a[0]), "r"(a[1]), "r"(a[2]), "r"(a[3]),
          "r"(b[0]), "r"(b[1]));
}

// ---------------- TF32 tensor-core GEMM (legacy mma.sync, cp.async 2-stage) ----------------
// C[M,N] = A[M,K] * B[N,K]^T (+= if ADD). Inputs pre-rounded to tf32.
// CTA tile 128x128, BK=32, 256 threads = 8 warps (4m x 2n), warp tile 32x64.
// smem: [m][k] layout, row stride 36 floats (conflict-free fragment LDS, 16B-aligned rows).
#define RS 36
#define STGF (128*RS)                 // floats per matrix per stage
#define SMEM_GEMM (4*STGF*4)          // 2 stages x (A+B) bytes = 73728

template<bool ADD>
__global__ void __launch_bounds__(256, 2) gemm_tc(
    const float* __restrict__ A, const float* __restrict__ B, float* __restrict__ C,
    int Kn, int Nn, long long sA, long long sB, long long sC)
{
    extern __shared__ __align__(16) float sm[];
    A += (long long)blockIdx.z * sA + (long long)(blockIdx.y * 128) * Kn;
    B += (long long)blockIdx.z * sB + (long long)(blockIdx.x * 128) * Kn;
    C += (long long)blockIdx.z * sC;

    const int tid = threadIdx.x, warp = tid >> 5, lane = tid & 31;
    const int gid = lane >> 2, tig = lane & 3;
    const int wm = (warp & 3) * 32;
    const int wn = (warp >> 2) * 64;

    float* const AsS[2] = { sm,            sm + STGF     };
    float* const BsS[2] = { sm + 2*STGF,   sm + 3*STGF   };

    float acc[2][8][4];
#pragma unroll
    for (int mt = 0; mt < 2; mt++)
#pragma unroll
        for (int nt = 0; nt < 8; nt++)
#pragma unroll
            for (int j = 0; j < 4; j++) acc[mt][nt][j] = 0.f;

    const int r0 = tid >> 3;          // 0..31
    const int c4 = (tid & 7) << 2;    // 0,4,...,28 (float offset of 16B segment)

    const uint32_t aS[2] = { smem_u32(AsS[0]), smem_u32(AsS[1]) };
    const uint32_t bS[2] = { smem_u32(BsS[0]), smem_u32(BsS[1]) };

    auto load = [&](int chunk, int s) {
        const float* Ag = A + chunk * 32;
        const float* Bg = B + chunk * 32;
#pragma unroll
        for (int it = 0; it < 4; it++) {
            int r = r0 + it * 32;
            uint32_t off = (uint32_t)(r * RS + c4) * 4u;
            cpasync16(aS[s] + off, Ag + (long long)r * Kn + c4);
            cpasync16(bS[s] + off, Bg + (long long)r * Kn + c4);
        }
        CP_COMMIT();
    };

    const int NC = Kn >> 5;
    load(0, 0);
    load(1, 1);

    for (int c = 0; c < NC; c++) {
        const int s = c & 1;
        if (c < NC - 1) { CP_WAIT1(); } else { CP_WAIT0(); }
        __syncthreads();

        const float* As = AsS[s];
        const float* Bs = BsS[s];
#pragma unroll
        for (int kk = 0; kk < 4; kk++) {
            const int kb = kk * 8;
            unsigned a[2][4], b[8][2];
#pragma unroll
            for (int mt = 0; mt < 2; mt++) {
                const float* ap = As + (wm + mt * 16 + gid) * RS;
                a[mt][0] = __float_as_uint(ap[kb + tig]);
                a[mt][1] = __float_as_uint(ap[8 * RS + kb + tig]);
                a[mt][2] = __float_as_uint(ap[kb + tig + 4]);
                a[mt][3] = __float_as_uint(ap[8 * RS + kb + tig + 4]);
            }
#pragma unroll
            for (int nt = 0; nt < 8; nt++) {
                const float* bp = Bs + (wn + nt * 8 + gid) * RS;
                b[nt][0] = __float_as_uint(bp[kb + tig]);
                b[nt][1] = __float_as_uint(bp[kb + tig + 4]);
            }
#pragma unroll
            for (int mt = 0; mt < 2; mt++)
#pragma unroll
                for (int nt = 0; nt < 8; nt++)
                    mma_tf32(acc[mt][nt], a[mt], b[nt]);
        }
        __syncthreads();

        if (c + 2 < NC) load(c + 2, s);
    }

    // epilogue
#pragma unroll
    for (int mt = 0; mt < 2; mt++) {
        int r0c = blockIdx.y * 128 + wm + mt * 16 + gid;
#pragma unroll
        for (int nt = 0; nt < 8; nt++) {
            int cc = blockIdx.x * 128 + wn + nt * 8 + 2 * tig;
            float* p0 = C + (long long)r0c * Nn + cc;
            float* p1 = p0 + 8 * (long long)Nn;
            if (ADD) {
                p0[0] += acc[mt][nt][0]; p0[1] += acc[mt][nt][1];
                p1[0] += acc[mt][nt][2]; p1[1] += acc[mt][nt][3];
            } else {
                p0[0] = acc[mt][nt][0]; p0[1] = acc[mt][nt][1];
                p1[0] = acc[mt][nt][2]; p1[1] = acc[mt][nt][3];
            }
        }
    }
}

// ---------------- RMSNorm (tf32-rounded output) ----------------
__global__ void rmsnorm_k(const float* __restrict__ x, const float* __restrict__ sc,
                          float* __restrict__ o)
{
    const int row = blockIdx.x;
    const float* xr = x + (long long)row * DD;
    float*       orw = o + (long long)row * DD;
    float s = 0.f;
    for (int j = threadIdx.x; j < DD; j += 256) { float v = xr[j]; s += v * v; }
    __shared__ float red[256];
    red[threadIdx.x] = s; __syncthreads();
    for (int t = 128; t > 0; t >>= 1) {
        if (threadIdx.x < t) red[threadIdx.x] += red[threadIdx.x + t];
        __syncthreads();
    }
    float r = rsqrtf(red[0] * (1.0f / DD) + EPSV);
    for (int j = threadIdx.x; j < DD; j += 256) orw[j] = f2tf_f(xr[j] * r * sc[j]);
}

// ---------------- RoPE + augmentation (tf32-rounded) ----------------
__global__ void rope_aug_k(const float* __restrict__ in, float* __restrict__ out)
{
    int idx = blockIdx.x * 256 + threadIdx.x;     // B*S*H*HALF threads
    int d = idx & 63;
    int h = (idx >> 6) & 15;
    int s = (idx >> 10) & 1023;
    int b = idx >> 20;
    long long m = (long long)b * SS + s;
    float q1 = in[m * DD + h * DHD + d];
    float q2 = in[m * DD + h * DHD + HALF + d];
    float inv = expf(-(float)d * (9.210340371976184f / 64.0f));
    float ang = (float)s * inv;
    float cs, sn; sincosf(ang, &sn, &cs);
    float o1 = q1 * cs - q2 * sn;
    float o2 = q1 * sn + q2 * cs;
    long long base = (((long long)(b * HH + h)) * SS + s) * KAUG;
    out[base + d]              = f2tf_f(o1);
    out[base + HALF + d]       = f2tf_f(o2);
    out[base + DHD + d]        = f2tf_f(SQLAM * o1 * o1);
    out[base + DHD + HALF + d] = f2tf_f(SQLAM * o2 * o2);
}

// ---------------- V transpose -> per-head [DHD, S] K-major (tf32-rounded) ----------------
__global__ void vt_k(const float* __restrict__ in, float* __restrict__ out)
{
    __shared__ float t[32][33];
    int bh = blockIdx.z;
    int b = bh >> 4, h = bh & 15;
    int s0 = blockIdx.x * 32, d0 = blockIdx.y * 32;
    int tx = threadIdx.x & 31, ty = threadIdx.x >> 5;   // 256 thr: ty 0..7
    for (int i = ty; i < 32; i += 8) {
        int s = s0 + i, d = d0 + tx;
        t[i][tx] = in[((long long)(b * SS + s)) * DD + h * DHD + d];
    }
    __syncthreads();
    for (int i = ty; i < 32; i += 8) {
        int d = d0 + i, s = s0 + tx;
        out[((long long)bh * DHD + d) * SS + s] = f2tf_f(t[tx][i]);
    }
}

// ---------------- causal softmax (tf32-rounded output) ----------------
__global__ void softmax_k(float* __restrict__ sc)
{
    long long row = blockIdx.x;
    int i = (int)(row % SS);
    float* p = sc + row * SS;
    int tid = threadIdx.x;
    __shared__ float red[256];

    float m = -1e30f;
    for (int j = tid; j <= i; j += 256) m = fmaxf(m, p[j] * SCALE);
    red[tid] = m; __syncthreads();
    for (int t = 128; t > 0; t >>= 1) {
        if (tid < t) red[tid] = fmaxf(red[tid], red[tid + t]);
        __syncthreads();
    }
    m = red[0]; __syncthreads();

    float sum = 0.f;
    for (int j = tid; j <= i; j += 256) {
        float e = expf(p[j] * SCALE - m);
        p[j] = e; sum += e;
    }
    red[tid] = sum; __syncthreads();
    for (int t = 128; t > 0; t >>= 1) {
        if (tid < t) red[tid] += red[tid + t];
        __syncthreads();
    }
    float inv = 1.f / red[0];
    for (int j = tid; j < SS; j += 256) p[j] = (j <= i) ? f2tf_f(p[j] * inv) : 0.f;
}

// ---------------- hadamard mix + transpose (tf32-rounded) ----------------
__global__ void mix_transpose_k(const float* __restrict__ ao, float* __restrict__ out)
{
    int idx = blockIdx.x * 256 + threadIdx.x;
    int d  = idx & 127;
    int s  = (idx >> 7) & 1023;
    int bh = idx >> 17;
    int h = bh & 15, b = bh >> 4;
    float v  = ao[idx];
    float pv = ao[(idx - d) | ((d + 127) & 127)];
    out[((long long)(b * SS + s)) * DD + h * DHD + d] = f2tf_f(v * (1.f + HS * pv));
}

// ---------------- elementwise ----------------
__global__ void copy_k(float* __restrict__ dst, const float* __restrict__ src, int n)
{ int i = blockIdx.x * 256 + threadIdx.x; if (i < n) dst[i] = src[i]; }

__global__ void round_k(float* __restrict__ dst, const float* __restrict__ src, int n)
{ int i = blockIdx.x * 256 + threadIdx.x; if (i < n) dst[i] = f2tf_f(src[i]); }

__global__ void silu_mul_k(float* __restrict__ g, const float* __restrict__ u, int n)
{
    int i = blockIdx.x * 256 + threadIdx.x;
    if (i < n) { float x = g[i]; g[i] = (x / (1.f + expf(-x))) * u[i]; }
}

__global__ void mix_row_k(const float* __restrict__ g, float* __restrict__ o)
{
    int i = blockIdx.x * 256 + threadIdx.x;
    int col  = i & (FF - 1);
    int prev = (i - col) | ((col + FF - 1) & (FF - 1));
    float v = g[i];
    o[i] = f2tf_f(v * (1.f + HS * g[prev]));
}

__global__ void x2_k(float* __restrict__ cur, const float* __restrict__ h1,
                     const float* __restrict__ x, int n)
{ int i = blockIdx.x * 256 + threadIdx.x; if (i < n) cur[i] = (1.f + BETA) * h1[i] - BETA * x[i]; }

__global__ void final_k(float* __restrict__ out, const float* __restrict__ h1,
                        const float* __restrict__ h2, int n)
{
    int i = blockIdx.x * 256 + threadIdx.x;
    if (i < n) {
        float v = ALPHA * h1[i] + (1.f - ALPHA) * h2[i];
        out[i] = fminf(fmaxf(v, -CLIPV), CLIPV);
    }
}

// ---------------- host orchestration ----------------
static void run_pass(const float* Wq, const float* Wk, const float* Wv, const float* Wo,
                     const float* Wg, const float* Wu, const float* Wd,
                     const float* na, const float* nb,
                     float* cur, float* xn, float* tmp,
                     float* qa, float* ka, float* vt, float* ao, float* sc,
                     float* gt, float* up)
{
    const int nMD = MM * DD, nMF = MM * FF;
    const dim3 gDD(DD/128, MM/128, 1);
    const dim3 gFF(FF/128, MM/128, 1);

    rmsnorm_k<<<MM, 256>>>(cur, na, xn);

    gemm_tc<false><<<gDD, 256, SMEM_GEMM>>>(xn, Wq, tmp, DD, DD, 0, 0, 0);
    rope_aug_k<<<(BB*SS*HH*HALF)/256, 256>>>(tmp, qa);
    gemm_tc<false><<<gDD, 256, SMEM_GEMM>>>(xn, Wk, tmp, DD, DD, 0, 0, 0);
    rope_aug_k<<<(BB*SS*HH*HALF)/256, 256>>>(tmp, ka);
    gemm_tc<false><<<gDD, 256, SMEM_GEMM>>>(xn, Wv, tmp, DD, DD, 0, 0, 0);
    vt_k<<<dim3(SS/32, DHD/32, BB*HH), 256>>>(tmp, vt);

    // scores: per head [S,S] = qa[S,256] * ka^T
    gemm_tc<false><<<dim3(SS/128, SS/128, BB*HH), 256, SMEM_GEMM>>>(
        qa, ka, sc, KAUG, SS,
        (long long)SS*KAUG, (long long)SS*KAUG, (long long)SS*SS);
    softmax_k<<<BB*HH*SS, 256>>>(sc);
    // O = P[S,S] * Vt[DHD,S]^T   per head
    gemm_tc<false><<<dim3(1, SS/128, BB*HH), 256, SMEM_GEMM>>>(
        sc, vt, ao, SS, DHD,
        (long long)SS*SS, (long long)SS*DHD, (long long)SS*DHD);

    mix_transpose_k<<<nMD/256, 256>>>(ao, tmp);
    gemm_tc<true><<<gDD, 256, SMEM_GEMM>>>(tmp, Wo, cur, DD, DD, 0, 0, 0);

    rmsnorm_k<<<MM, 256>>>(cur, nb, xn);
    gemm_tc<false><<<gFF, 256, SMEM_GEMM>>>(xn, Wg, gt, DD, FF, 0, 0, 0);
    gemm_tc<false><<<gFF, 256, SMEM_GEMM>>>(xn, Wu, up, DD, FF, 0, 0, 0);
    silu_mul_k<<<(nMF+255)/256, 256>>>(gt, up, nMF);
    mix_row_k<<<nMF/256, 256>>>(gt, up);
    gemm_tc<true><<<gDD, 256, SMEM_GEMM>>>(up, Wd, cur, FF, DD, 0, 0, 0);
}

extern "C" void kernel_launch(void* const* d_in, const int* in_sizes, int n_in,
                              void* d_out, int out_size)
{
    (void)in_sizes; (void)n_in; (void)out_size;
    const float* x   = (const float*)d_in[0];
    const float* Wq0 = (const float*)d_in[1];
    const float* Wk0 = (const float*)d_in[2];
    const float* Wv0 = (const float*)d_in[3];
    const float* Wo0 = (const float*)d_in[4];
    // d_in[5] = gate_w: unused (rotate_half invariance => o2 == o1)
    const float* n1 = (const float*)d_in[6];
    const float* n2 = (const float*)d_in[7];
    const float* n3 = (const float*)d_in[8];
    const float* n4 = (const float*)d_in[9];
    const float* Wg0 = (const float*)d_in[10];
    const float* Wu0 = (const float*)d_in[11];
    const float* Wd0 = (const float*)d_in[12];
    float* out = (float*)d_out;

    cudaFuncSetAttribute(gemm_tc<false>, cudaFuncAttributeMaxDynamicSharedMemorySize, SMEM_GEMM);
    cudaFuncSetAttribute(gemm_tc<true>,  cudaFuncAttributeMaxDynamicSharedMemorySize, SMEM_GEMM);

    float *xn, *tmp, *cur, *h1, *qa, *ka, *vt, *ao, *sc, *gt, *up;
    float *wq, *wk, *wv, *wo, *wg, *wu, *wd;
    cudaGetSymbolAddress((void**)&xn,  g_xn);
    cudaGetSymbolAddress((void**)&tmp, g_tmp);
    cudaGetSymbolAddress((void**)&cur, g_cur);
    cudaGetSymbolAddress((void**)&h1,  g_h1);
    cudaGetSymbolAddress((void**)&qa,  g_qa);
    cudaGetSymbolAddress((void**)&ka,  g_ka);
    cudaGetSymbolAddress((void**)&vt,  g_vt);
    cudaGetSymbolAddress((void**)&ao,  g_ao);
    cudaGetSymbolAddress((void**)&sc,  g_sc);
    cudaGetSymbolAddress((void**)&gt,  g_gt);
    cudaGetSymbolAddress((void**)&up,  g_up);
    cudaGetSymbolAddress((void**)&wq,  g_wq);
    cudaGetSymbolAddress((void**)&wk,  g_wk);
    cudaGetSymbolAddress((void**)&wv,  g_wv);
    cudaGetSymbolAddress((void**)&wo,  g_wo);
    cudaGetSymbolAddress((void**)&wg,  g_wg);
    cudaGetSymbolAddress((void**)&wu,  g_wu);
    cudaGetSymbolAddress((void**)&wd,  g_wd);

    const int nMD = MM * DD;

    // pre-round weights to tf32 (so GEMM needs no per-element conversion)
    round_k<<<(DD*DD+255)/256, 256>>>(wq, Wq0, DD*DD);
    round_k<<<(DD*DD+255)/256, 256>>>(wk, Wk0, DD*DD);
    round_k<<<(DD*DD+255)/256, 256>>>(wv, Wv0, DD*DD);
    round_k<<<(DD*DD+255)/256, 256>>>(wo, Wo0, DD*DD);
    round_k<<<(FF*DD+255)/256, 256>>>(wg, Wg0, FF*DD);
    round_k<<<(FF*DD+255)/256, 256>>>(wu, Wu0, FF*DD);
    round_k<<<(FF*DD+255)/256, 256>>>(wd, Wd0, FF*DD);

    // pass 1
    copy_k<<<(nMD+255)/256, 256>>>(cur, x, nMD);
    run_pass(wq, wk, wv, wo, wg, wu, wd, n1, n2,
             cur, xn, tmp, qa, ka, vt, ao, sc, gt, up);
    copy_k<<<(nMD+255)/256, 256>>>(h1, cur, nMD);

    // x2 = h1 + beta*(h1 - x)
    x2_k<<<(nMD+255)/256, 256>>>(cur, h1, x, nMD);

    // pass 2
    run_pass(wq, wk, wv, wo, wg, wu, wd, n3, n4,
             cur, xn, tmp, qa, ka, vt, ao, sc, gt, up);

    // out = clip(alpha*h1 + (1-alpha)*h2)
    final_k<<<(nMD+255)/256, 256>>>(out, h1, cur, nMD);
}

// round 5
// speedup vs baseline: 6.5726x; 2.3329x over previous
#include <cuda_runtime.h>
#include <cuda_fp16.h>
#include <math.h>
#include <stdint.h>

// ---------------- problem constants ----------------
#define BB   2
#define SS   1024
#define DD   2048
#define HH   16
#define FF   8192
#define DHD  128
#define HALF 64
#define MM   (BB*SS)          // 2048 rows
#define KAUG (2*DHD)          // 256 augmented K dim

#define HS    0.05f
#define BETA  0.3f
#define ALPHA 0.5f
#define CLIPV 10.0f
#define EPSV  1e-6f
#define SCALE 0.08838834764831845f   // 1/sqrt(128)
#define SQLAM 0.31622776601683794f   // sqrt(0.1)

// ---------------- static device scratch ----------------
static __device__ __align__(128) __half g_xn  [MM*DD];          // rmsnorm out / mix out (GEMM A)
static __device__ __align__(128) float  g_tmp [MM*3*DD];        // QKV GEMM out
static __device__ __align__(128) float  g_cur [MM*DD];
static __device__ __align__(128) float  g_h1  [MM*DD];
static __device__ __align__(128) __half g_qa  [BB*HH*SS*KAUG];
static __device__ __align__(128) __half g_ka  [BB*HH*SS*KAUG];
static __device__ __align__(128) __half g_vt  [BB*HH*DHD*SS];   // per-head [DHD, S]
static __device__ __align__(128) float  g_ao  [BB*HH*SS*DHD];
static __device__ __align__(128) float  g_sc  [(long long)BB*HH*SS*SS];  // scores fp32
static __device__ __align__(128) __half g_ph  [(long long)BB*HH*SS*SS];  // probs fp16
static __device__ __align__(128) float  g_gu  [MM*2*FF];        // FFN gate|up GEMM out
static __device__ __align__(128) __half g_hh  [MM*FF];          // FFN hidden (GEMM A)
// fp16 weights (stacked)
static __device__ __align__(128) __half g_wqkv[3*DD*DD];
static __device__ __align__(128) __half g_wo  [DD*DD];
static __device__ __align__(128) __half g_wgu [2*FF*DD];
static __device__ __align__(128) __half g_wd  [DD*FF];

// ---------------- helpers ----------------
__device__ __forceinline__ uint32_t smem_u32(const void* p) {
    uint32_t a;
    asm("{ .reg .u64 t; cvta.to.shared.u64 t, %1; cvt.u32.u64 %0, t; }" : "=r"(a) : "l"(p));
    return a;
}
__device__ __forceinline__ void cpasync16(uint32_t dst, const void* src) {
    asm volatile("cp.async.cg.shared.global [%0], [%1], 16;" :: "r"(dst), "l"(src));
}
#define CP_COMMIT()  asm volatile("cp.async.commit_group;" ::: "memory")
#define CP_WAIT1()   asm volatile("cp.async.wait_group 1;" ::: "memory")
#define CP_WAIT0()   asm volatile("cp.async.wait_group 0;" ::: "memory")

__device__ __forceinline__ void ldmx4(uint32_t* r, uint32_t addr) {
    asm volatile("ldmatrix.sync.aligned.m8n8.x4.shared.b16 {%0,%1,%2,%3}, [%4];"
        : "=r"(r[0]), "=r"(r[1]), "=r"(r[2]), "=r"(r[3]) : "r"(addr));
}
__device__ __forceinline__ void mma16816(float* c, const uint32_t* a, uint32_t b0, uint32_t b1) {
    asm volatile("mma.sync.aligned.m16n8k16.row.col.f32.f16.f16.f32 "
        "{%0,%1,%2,%3}, {%4,%5,%6,%7}, {%8,%9}, {%0,%1,%2,%3};"
        : "+f"(c[0]), "+f"(c[1]), "+f"(c[2]), "+f"(c[3])
        : "r"(a[0]), "r"(a[1]), "r"(a[2]), "r"(a[3]), "r"(b0), "r"(b1));
}

// ---------------- fp16 tensor-core GEMM ----------------
// C[M,N](f32) = A[M,K](f16) * B[N,K](f16)^T  (+= if ADD)
// CTA tile 128x128, chunk = 64 halves (128B rows), 2-stage cp.async.
// 8 warps (4m x 2n), warp tile 32x64, ldmatrix.x4 fragments, XOR-swizzled smem.
// TRI: blockIdx.x enumerates lower-triangle (i,j) blocks (causal scores).
// PVK: K limited to (blockIdx.y+1)*128 halves (causal PV).
#define HSTAGE 32768    // 256 rows * 128B per stage (A:128 rows, B:128 rows)

template<bool ADD, bool TRI, bool PVK>
__global__ void __launch_bounds__(256, 2) hgemm(
    const __half* __restrict__ A, const __half* __restrict__ B, float* __restrict__ C,
    int Kn, int Nn, long long sA, long long sB, long long sC)
{
    extern __shared__ __align__(128) char sm[];
    const uint32_t sbase = smem_u32(sm);

    int bi, bj;
    if (TRI) {
        int x = blockIdx.x, i = 0;
        while ((i + 1) * (i + 2) / 2 <= x) i++;
        bi = i; bj = x - i * (i + 1) / 2;
    } else { bi = blockIdx.y; bj = blockIdx.x; }

    A += (long long)blockIdx.z * sA + (long long)(bi * 128) * Kn;
    B += (long long)blockIdx.z * sB + (long long)(bj * 128) * Kn;
    C += (long long)blockIdx.z * sC;

    const int NC = PVK ? 2 * (blockIdx.y + 1) : (Kn >> 6);

    const int tid = threadIdx.x, warp = tid >> 5, lane = tid & 31;
    const int gid = lane >> 2, tig = lane & 3;
    const int wm = (warp & 3) * 32, wn = (warp >> 2) * 64;

    // ldmatrix per-lane geometry
    const int mi = lane >> 3, ri = lane & 7;
    const int fro = (mi & 1) * 8 + ri;     // row offset within 16-row fragment
    const int khalf = mi >> 1;             // which 8-col half (0/1)

    float acc[2][8][4];
#pragma unroll
    for (int mt = 0; mt < 2; mt++)
#pragma unroll
        for (int nt = 0; nt < 8; nt++)
#pragma unroll
            for (int j = 0; j < 4; j++) acc[mt][nt][j] = 0.f;

    const int lr = tid >> 3;        // loader row base 0..31
    const int lseg = tid & 7;       // 16B segment 0..7

    auto load = [&](int chunk, int s) {
        const uint32_t st = sbase + (uint32_t)s * HSTAGE;
        const __half* Ag = A + chunk * 64;
        const __half* Bg = B + chunk * 64;
#pragma unroll
        for (int it = 0; it < 4; it++) {
            int r = lr + it * 32;
            uint32_t off = (uint32_t)(r * 128 + ((lseg ^ (r & 7)) << 4));
            cpasync16(st + off,         Ag + (long long)r * Kn + lseg * 8);
            cpasync16(st + 16384 + off, Bg + (long long)r * Kn + lseg * 8);
        }
        CP_COMMIT();
    };

    load(0, 0);
    load(1, 1);

    // precompute fragment row bases
    const int arow[2] = { wm + fro, wm + 16 + fro };
    const int brow[4] = { wn + fro, wn + 16 + fro, wn + 32 + fro, wn + 48 + fro };

    for (int c = 0; c < NC; c++) {
        const int s = c & 1;
        if (c < NC - 1) { CP_WAIT1(); } else { CP_WAIT0(); }
        __syncthreads();

        const uint32_t st = sbase + (uint32_t)s * HSTAGE;
#pragma unroll
        for (int kb = 0; kb < 64; kb += 16) {
            const int ks = (kb >> 3) + khalf;
            uint32_t a[2][4], b[4][4];
#pragma unroll
            for (int mt = 0; mt < 2; mt++) {
                int r = arow[mt];
                ldmx4(a[mt], st + (uint32_t)(r * 128 + ((ks ^ (r & 7)) << 4)));
            }
#pragma unroll
            for (int np = 0; np < 4; np++) {
                int r = brow[np];
                ldmx4(b[np], st + 16384u + (uint32_t)(r * 128 + ((ks ^ (r & 7)) << 4)));
            }
#pragma unroll
            for (int mt = 0; mt < 2; mt++)
#pragma unroll
                for (int nt = 0; nt < 8; nt++)
                    mma16816(acc[mt][nt], a[mt], b[nt >> 1][nt & 1], b[nt >> 1][2 + (nt & 1)]);
        }
        __syncthreads();
        if (c + 2 < NC) load(c + 2, s);
    }

    // epilogue
#pragma unroll
    for (int mt = 0; mt < 2; mt++) {
        int r0 = bi * 128 + wm + mt * 16 + gid;
#pragma unroll
        for (int nt = 0; nt < 8; nt++) {
            int cc = bj * 128 + wn + nt * 8 + 2 * tig;
            float* p0 = C + (long long)r0 * Nn + cc;
            float* p1 = p0 + 8 * (long long)Nn;
            if (ADD) {
                p0[0] += acc[mt][nt][0]; p0[1] += acc[mt][nt][1];
                p1[0] += acc[mt][nt][2]; p1[1] += acc[mt][nt][3];
            } else {
                p0[0] = acc[mt][nt][0]; p0[1] = acc[mt][nt][1];
                p1[0] = acc[mt][nt][2]; p1[1] = acc[mt][nt][3];
            }
        }
    }
}

// ---------------- RMSNorm -> fp16 ----------------
__global__ void rmsnorm_k(const float* __restrict__ x, const float* __restrict__ sc,
                          __half* __restrict__ o)
{
    const int row = blockIdx.x;
    const float* xr = x + (long long)row * DD;
    __half*      orw = o + (long long)row * DD;
    float s = 0.f;
    for (int j = threadIdx.x; j < DD; j += 256) { float v = xr[j]; s += v * v; }
    __shared__ float red[256];
    red[threadIdx.x] = s; __syncthreads();
    for (int t = 128; t > 0; t >>= 1) {
        if (threadIdx.x < t) red[threadIdx.x] += red[threadIdx.x + t];
        __syncthreads();
    }
    float r = rsqrtf(red[0] * (1.0f / DD) + EPSV);
    for (int j = threadIdx.x; j < DD; j += 256) orw[j] = __float2half(xr[j] * r * sc[j]);
}

// ---------------- RoPE + augment (Q and K together) from tmp[M,3D] ----------------
__global__ void rope_aug2_k(const float* __restrict__ t,
                            __half* __restrict__ qa, __half* __restrict__ ka)
{
    int idx = blockIdx.x * 256 + threadIdx.x;     // B*S*H*HALF threads
    int d = idx & 63;
    int h = (idx >> 6) & 15;
    int s = (idx >> 10) & 1023;
    int b = idx >> 20;
    const float* row = t + ((long long)b * SS + s) * (3 * DD);
    float q1 = row[h * DHD + d];
    float q2 = row[h * DHD + HALF + d];
    float k1 = row[DD + h * DHD + d];
    float k2 = row[DD + h * DHD + HALF + d];
    float inv = expf(-(float)d * (9.210340371976184f / 64.0f));
    float ang = (float)s * inv;
    float cs, sn; sincosf(ang, &sn, &cs);
    long long base = (((long long)(b * HH + h)) * SS + s) * KAUG;
    float qo1 = q1 * cs - q2 * sn, qo2 = q1 * sn + q2 * cs;
    float ko1 = k1 * cs - k2 * sn, ko2 = k1 * sn + k2 * cs;
    qa[base + d]              = __float2half(qo1);
    qa[base + HALF + d]       = __float2half(qo2);
    qa[base + DHD + d]        = __float2half(SQLAM * qo1 * qo1);
    qa[base + DHD + HALF + d] = __float2half(SQLAM * qo2 * qo2);
    ka[base + d]              = __float2half(ko1);
    ka[base + HALF + d]       = __float2half(ko2);
    ka[base + DHD + d]        = __float2half(SQLAM * ko1 * ko1);
    ka[base + DHD + HALF + d] = __float2half(SQLAM * ko2 * ko2);
}

// ---------------- V transpose from tmp[M,3D] -> per-head [DHD,S] fp16 ----------------
__global__ void vt_k(const float* __restrict__ t, __half* __restrict__ out)
{
    __shared__ float tl[32][33];
    int bh = blockIdx.z;
    int b = bh >> 4, h = bh & 15;
    int s0 = blockIdx.x * 32, d0 = blockIdx.y * 32;
    int tx = threadIdx.x & 31, ty = threadIdx.x >> 5;
    for (int i = ty; i < 32; i += 8) {
        int s = s0 + i, d = d0 + tx;
        tl[i][tx] = t[((long long)(b * SS + s)) * (3 * DD) + 2 * DD + h * DHD + d];
    }
    __syncthreads();
    for (int i = ty; i < 32; i += 8) {
        int d = d0 + i, s = s0 + tx;
        out[((long long)bh * DHD + d) * SS + s] = __float2half(tl[tx][i]);
    }
}

// ---------------- causal softmax: fp32 scores -> fp16 probs ----------------
__global__ void softmax_k(const float* __restrict__ sc, __half* __restrict__ ph)
{
    long long row = blockIdx.x;
    int i = (int)(row % SS);
    int lim = i | 127;                     // covers what PV reads for this q-block
    const float* p = sc + row * SS;
    __half* q = ph + row * SS;
    int tid = threadIdx.x;
    __shared__ float red[256];

    float m = -1e30f;
    for (int j = tid; j <= i; j += 256) m = fmaxf(m, p[j] * SCALE);
    red[tid] = m; __syncthreads();
    for (int t = 128; t > 0; t >>= 1) {
        if (tid < t) red[tid] = fmaxf(red[tid], red[tid + t]);
        __syncthreads();
    }
    m = red[0]; __syncthreads();

    float sum = 0.f;
    for (int j = tid; j <= i; j += 256) sum += expf(p[j] * SCALE - m);
    red[tid] = sum; __syncthreads();
    for (int t = 128; t > 0; t >>= 1) {
        if (tid < t) red[tid] += red[tid + t];
        __syncthreads();
    }
    float inv = 1.f / red[0];
    for (int j = tid; j <= lim; j += 256)
        q[j] = (j <= i) ? __float2half(expf(p[j] * SCALE - m) * inv) : __half(0.f);
}

// ---------------- hadamard mix + transpose -> fp16 [M,D] ----------------
__global__ void mix_transpose_k(const float* __restrict__ ao, __half* __restrict__ out)
{
    int idx = blockIdx.x * 256 + threadIdx.x;
    int d  = idx & 127;
    int s  = (idx >> 7) & 1023;
    int bh = idx >> 17;
    int h = bh & 15, b = bh >> 4;
    float v  = ao[idx];
    float pv = ao[(idx - d) | ((d + 127) & 127)];
    out[((long long)(b * SS + s)) * DD + h * DHD + d] = __float2half(v * (1.f + HS * pv));
}

// ---------------- fused silu*up + hadamard mix -> fp16 hidden ----------------
__global__ void silu_mix_k(const float* __restrict__ gu, __half* __restrict__ hh)
{
    int i = blockIdx.x * 256 + threadIdx.x;       // M*F threads
    int m = i >> 13;                               // F = 8192
    int c = i & (FF - 1);
    const float* row = gu + (long long)m * (2 * FF);
    int pc = (c + FF - 1) & (FF - 1);
    float g  = row[c],  u  = row[FF + c];
    float g2 = row[pc], u2 = row[FF + pc];
    float h  = g  / (1.f + expf(-g))  * u;
    float h2 = g2 / (1.f + expf(-g2)) * u2;
    hh[i] = __float2half(h * (1.f + HS * h2));
}

// ---------------- misc elementwise ----------------
__global__ void copy_k(float* __restrict__ dst, const float* __restrict__ src, int n)
{ int i = blockIdx.x * 256 + threadIdx.x; if (i < n) dst[i] = src[i]; }

__global__ void w2h_k(__half* __restrict__ dst, const float* __restrict__ src, int n)
{ int i = blockIdx.x * 256 + threadIdx.x; if (i < n) dst[i] = __float2half(src[i]); }

__global__ void x2_k(float* __restrict__ cur, const float* __restrict__ h1,
                     const float* __restrict__ x, int n)
{ int i = blockIdx.x * 256 + threadIdx.x; if (i < n) cur[i] = (1.f + BETA) * h1[i] - BETA * x[i]; }

__global__ void final_k(float* __restrict__ out, const float* __restrict__ h1,
                        const float* __restrict__ h2, int n)
{
    int i = blockIdx.x * 256 + threadIdx.x;
    if (i < n) {
        float v = ALPHA * h1[i] + (1.f - ALPHA) * h2[i];
        out[i] = fminf(fmaxf(v, -CLIPV), CLIPV);
    }
}

// ---------------- host orchestration ----------------
#define HSMEM (2*HSTAGE)

static void run_pass(const __half* wqkv, const __half* wo, const __half* wgu, const __half* wd,
                     const float* na, const float* nb,
                     float* cur, __half* xn, float* tmp,
                     __half* qa, __half* ka, __half* vt, float* ao,
                     float* sc, __half* ph, float* gu, __half* hh)
{
    const int nMD = MM * DD, nMF = MM * FF;

    rmsnorm_k<<<MM, 256>>>(cur, na, xn);

    // fused QKV: [M, 3D] = xn * wqkv^T
    hgemm<false,false,false><<<dim3(3*DD/128, MM/128, 1), 256, HSMEM>>>(
        xn, wqkv, tmp, DD, 3*DD, 0, 0, 0);
    rope_aug2_k<<<(BB*SS*HH*HALF)/256, 256>>>(tmp, qa, ka);
    vt_k<<<dim3(SS/32, DHD/32, BB*HH), 256>>>(tmp, vt);

    // causal scores: lower-triangle blocks only
    hgemm<false,true,false><<<dim3(36, 1, BB*HH), 256, HSMEM>>>(
        qa, ka, sc, KAUG, SS,
        (long long)SS*KAUG, (long long)SS*KAUG, (long long)SS*SS);
    softmax_k<<<BB*HH*SS, 256>>>(sc, ph);
    // PV with causal K truncation
    hgemm<false,false,true><<<dim3(1, SS/128, BB*HH), 256, HSMEM>>>(
        ph, vt, ao, SS, DHD,
        (long long)SS*SS, (long long)SS*DHD, (long long)SS*DHD);

    mix_transpose_k<<<nMD/256, 256>>>(ao, xn);
    hgemm<true,false,false><<<dim3(DD/128, MM/128, 1), 256, HSMEM>>>(
        xn, wo, cur, DD, DD, 0, 0, 0);

    rmsnorm_k<<<MM, 256>>>(cur, nb, xn);
    // fused gate|up: [M, 2F]
    hgemm<false,false,false><<<dim3(2*FF/128, MM/128, 1), 256, HSMEM>>>(
        xn, wgu, gu, DD, 2*FF, 0, 0, 0);
    silu_mix_k<<<nMF/256, 256>>>(gu, hh);
    hgemm<true,false,false><<<dim3(DD/128, MM/128, 1), 256, HSMEM>>>(
        hh, wd, cur, FF, DD, 0, 0, 0);
}

extern "C" void kernel_launch(void* const* d_in, const int* in_sizes, int n_in,
                              void* d_out, int out_size)
{
    (void)in_sizes; (void)n_in; (void)out_size;
    const float* x   = (const float*)d_in[0];
    const float* Wq0 = (const float*)d_in[1];
    const float* Wk0 = (const float*)d_in[2];
    const float* Wv0 = (const float*)d_in[3];
    const float* Wo0 = (const float*)d_in[4];
    // d_in[5] = gate_w: unused (rotate_half invariance => o2 == o1)
    const float* n1 = (const float*)d_in[6];
    const float* n2 = (const float*)d_in[7];
    const float* n3 = (const float*)d_in[8];
    const float* n4 = (const float*)d_in[9];
    const float* Wg0 = (const float*)d_in[10];
    const float* Wu0 = (const float*)d_in[11];
    const float* Wd0 = (const float*)d_in[12];
    float* out = (float*)d_out;

    cudaFuncSetAttribute(hgemm<false,false,false>, cudaFuncAttributeMaxDynamicSharedMemorySize, HSMEM);
    cudaFuncSetAttribute(hgemm<true,false,false>,  cudaFuncAttributeMaxDynamicSharedMemorySize, HSMEM);
    cudaFuncSetAttribute(hgemm<false,true,false>,  cudaFuncAttributeMaxDynamicSharedMemorySize, HSMEM);
    cudaFuncSetAttribute(hgemm<false,false,true>,  cudaFuncAttributeMaxDynamicSharedMemorySize, HSMEM);

    __half *xn, *qa, *ka, *vt, *ph, *hh, *wqkv, *wo, *wgu, *wd;
    float *tmp, *cur, *h1, *ao, *sc, *gu;
    cudaGetSymbolAddress((void**)&xn,  g_xn);
    cudaGetSymbolAddress((void**)&tmp, g_tmp);
    cudaGetSymbolAddress((void**)&cur, g_cur);
    cudaGetSymbolAddress((void**)&h1,  g_h1);
    cudaGetSymbolAddress((void**)&qa,  g_qa);
    cudaGetSymbolAddress((void**)&ka,  g_ka);
    cudaGetSymbolAddress((void**)&vt,  g_vt);
    cudaGetSymbolAddress((void**)&ao,  g_ao);
    cudaGetSymbolAddress((void**)&sc,  g_sc);
    cudaGetSymbolAddress((void**)&ph,  g_ph);
    cudaGetSymbolAddress((void**)&gu,  g_gu);
    cudaGetSymbolAddress((void**)&hh,  g_hh);
    cudaGetSymbolAddress((void**)&wqkv,g_wqkv);
    cudaGetSymbolAddress((void**)&wo,  g_wo);
    cudaGetSymbolAddress((void**)&wgu, g_wgu);
    cudaGetSymbolAddress((void**)&wd,  g_wd);

    const int nMD = MM * DD;

    // weights -> fp16 (stacked)
    w2h_k<<<(DD*DD+255)/256, 256>>>(wqkv,            Wq0, DD*DD);
    w2h_k<<<(DD*DD+255)/256, 256>>>(wqkv + DD*DD,    Wk0, DD*DD);
    w2h_k<<<(DD*DD+255)/256, 256>>>(wqkv + 2*DD*DD,  Wv0, DD*DD);
    w2h_k<<<(DD*DD+255)/256, 256>>>(wo,              Wo0, DD*DD);
    w2h_k<<<(FF*DD+255)/256, 256>>>(wgu,             Wg0, FF*DD);
    w2h_k<<<(FF*DD+255)/256, 256>>>(wgu + FF*DD,     Wu0, FF*DD);
    w2h_k<<<(FF*DD+255)/256, 256>>>(wd,              Wd0, FF*DD);

    // pass 1
    copy_k<<<(nMD+255)/256, 256>>>(cur, x, nMD);
    run_pass(wqkv, wo, wgu, wd, n1, n2, cur, xn, tmp, qa, ka, vt, ao, sc, ph, gu, hh);
    copy_k<<<(nMD+255)/256, 256>>>(h1, cur, nMD);

    // x2 = h1 + beta*(h1 - x)
    x2_k<<<(nMD+255)/256, 256>>>(cur, h1, x, nMD);

    // pass 2
    run_pass(wqkv, wo, wgu, wd, n3, n4, cur, xn, tmp, qa, ka, vt, ao, sc, ph, gu, hh);

    // out = clip(alpha*h1 + (1-alpha)*h2)
    final_k<<<(nMD+255)/256, 256>>>(out, h1, cur, nMD);
}

// round 6
// speedup vs baseline: 7.0545x; 1.0733x over previous
#include <cuda_runtime.h>
#include <cuda_fp16.h>
#include <math.h>
#include <stdint.h>

// ---------------- problem constants ----------------
#define BB   2
#define SS   1024
#define DD   2048
#define HH   16
#define FF   8192
#define DHD  128
#define HALF 64
#define MM   (BB*SS)          // 2048 rows
#define KAUG (2*DHD)          // 256 augmented K dim

#define HS    0.05f
#define BETA  0.3f
#define ALPHA 0.5f
#define CLIPV 10.0f
#define EPSV  1e-6f
#define SCALE 0.08838834764831845f   // 1/sqrt(128)
#define SQLAM 0.31622776601683794f   // sqrt(0.1)

// ---------------- static device scratch ----------------
static __device__ __align__(128) __half g_xn  [MM*DD];          // rmsnorm/mix out (GEMM A)
static __device__ __align__(128) __half g_tmp [MM*3*DD];        // QKV GEMM out (fp16)
static __device__ __align__(128) float  g_cur [MM*DD];
static __device__ __align__(128) float  g_h1  [MM*DD];
static __device__ __align__(128) __half g_qa  [BB*HH*SS*KAUG];
static __device__ __align__(128) __half g_ka  [BB*HH*SS*KAUG];
static __device__ __align__(128) __half g_vt  [BB*HH*DHD*SS];   // per-head [DHD, S]
static __device__ __align__(128) float  g_ao  [BB*HH*SS*DHD];   // unnormalized PV out
static __device__ __align__(128) float  g_inv [BB*HH*SS];       // per-row 1/sum
static __device__ __align__(128) float  g_sc  [(long long)BB*HH*SS*SS];  // scores fp32
static __device__ __align__(128) __half g_ph  [(long long)BB*HH*SS*SS];  // unnorm probs fp16
static __device__ __align__(128) __half g_gu  [MM*2*FF];        // FFN gate|up out (fp16)
static __device__ __align__(128) __half g_hh  [MM*FF];          // FFN hidden (GEMM A)
// fp16 weights (stacked)
static __device__ __align__(128) __half g_wqkv[3*DD*DD];
static __device__ __align__(128) __half g_wo  [DD*DD];
static __device__ __align__(128) __half g_wgu [2*FF*DD];
static __device__ __align__(128) __half g_wd  [DD*FF];

// ---------------- helpers ----------------
__device__ __forceinline__ uint32_t smem_u32(const void* p) {
    uint32_t a;
    asm("{ .reg .u64 t; cvta.to.shared.u64 t, %1; cvt.u32.u64 %0, t; }" : "=r"(a) : "l"(p));
    return a;
}
__device__ __forceinline__ void cpasync16(uint32_t dst, const void* src) {
    asm volatile("cp.async.cg.shared.global [%0], [%1], 16;" :: "r"(dst), "l"(src));
}
#define CP_COMMIT()  asm volatile("cp.async.commit_group;" ::: "memory")
#define CP_WAIT1()   asm volatile("cp.async.wait_group 1;" ::: "memory")
#define CP_WAIT0()   asm volatile("cp.async.wait_group 0;" ::: "memory")

__device__ __forceinline__ void ldmx4(uint32_t* r, uint32_t addr) {
    asm volatile("ldmatrix.sync.aligned.m8n8.x4.shared.b16 {%0,%1,%2,%3}, [%4];"
        : "=r"(r[0]), "=r"(r[1]), "=r"(r[2]), "=r"(r[3]) : "r"(addr));
}
__device__ __forceinline__ void mma16816(float* c, const uint32_t* a, uint32_t b0, uint32_t b1) {
    asm volatile("mma.sync.aligned.m16n8k16.row.col.f32.f16.f16.f32 "
        "{%0,%1,%2,%3}, {%4,%5,%6,%7}, {%8,%9}, {%0,%1,%2,%3};"
        : "+f"(c[0]), "+f"(c[1]), "+f"(c[2]), "+f"(c[3])
        : "r"(a[0]), "r"(a[1]), "r"(a[2]), "r"(a[3]), "r"(b0), "r"(b1));
}

// ---------------- fp16 tensor-core GEMM ----------------
// C[M,N](TO) = A[M,K](f16) * B[N,K](f16)^T  (+= if ADD; ADD only with TO=float)
// CTA tile 128x128, chunk = 64 halves (128B rows), 2-stage cp.async.
// 8 warps (4m x 2n), warp tile 32x64, ldmatrix.x4 fragments, XOR-swizzled smem.
// TRI: blockIdx.x enumerates lower-triangle (i,j) blocks (causal scores).
// PVK: K limited to (blockIdx.y+1)*128 halves (causal PV).
#define HSTAGE 32768    // A:128 rows + B:128 rows, 128B each

template<typename TO, bool ADD, bool TRI, bool PVK>
__global__ void __launch_bounds__(256, 2) hgemm(
    const __half* __restrict__ A, const __half* __restrict__ B, TO* __restrict__ C,
    int Kn, int Nn, long long sA, long long sB, long long sC)
{
    extern __shared__ __align__(128) char sm[];
    const uint32_t sbase = smem_u32(sm);

    int bi, bj;
    if (TRI) {
        int x = blockIdx.x, i = 0;
        while ((i + 1) * (i + 2) / 2 <= x) i++;
        bi = i; bj = x - i * (i + 1) / 2;
    } else { bi = blockIdx.y; bj = blockIdx.x; }

    A += (long long)blockIdx.z * sA + (long long)(bi * 128) * Kn;
    B += (long long)blockIdx.z * sB + (long long)(bj * 128) * Kn;
    C += (long long)blockIdx.z * sC;

    const int NC = PVK ? 2 * (blockIdx.y + 1) : (Kn >> 6);

    const int tid = threadIdx.x, warp = tid >> 5, lane = tid & 31;
    const int gid = lane >> 2, tig = lane & 3;
    const int wm = (warp & 3) * 32, wn = (warp >> 2) * 64;

    const int mi = lane >> 3, ri = lane & 7;
    const int fro = (mi & 1) * 8 + ri;
    const int khalf = mi >> 1;

    float acc[2][8][4];
#pragma unroll
    for (int mt = 0; mt < 2; mt++)
#pragma unroll
        for (int nt = 0; nt < 8; nt++)
#pragma unroll
            for (int j = 0; j < 4; j++) acc[mt][nt][j] = 0.f;

    const int lr = tid >> 3;
    const int lseg = tid & 7;

    auto load = [&](int chunk, int s) {
        const uint32_t st = sbase + (uint32_t)s * HSTAGE;
        const __half* Ag = A + chunk * 64;
        const __half* Bg = B + chunk * 64;
#pragma unroll
        for (int it = 0; it < 4; it++) {
            int r = lr + it * 32;
            uint32_t off = (uint32_t)(r * 128 + ((lseg ^ (r & 7)) << 4));
            cpasync16(st + off,         Ag + (long long)r * Kn + lseg * 8);
            cpasync16(st + 16384 + off, Bg + (long long)r * Kn + lseg * 8);
        }
        CP_COMMIT();
    };

    load(0, 0);
    load(1, 1);

    const int arow[2] = { wm + fro, wm + 16 + fro };
    const int brow[4] = { wn + fro, wn + 16 + fro, wn + 32 + fro, wn + 48 + fro };

    for (int c = 0; c < NC; c++) {
        const int s = c & 1;
        if (c < NC - 1) { CP_WAIT1(); } else { CP_WAIT0(); }
        __syncthreads();

        const uint32_t st = sbase + (uint32_t)s * HSTAGE;
#pragma unroll
        for (int kb = 0; kb < 64; kb += 16) {
            const int ks = (kb >> 3) + khalf;
            uint32_t a[2][4], b[4][4];
#pragma unroll
            for (int mt = 0; mt < 2; mt++) {
                int r = arow[mt];
                ldmx4(a[mt], st + (uint32_t)(r * 128 + ((ks ^ (r & 7)) << 4)));
            }
#pragma unroll
            for (int np = 0; np < 4; np++) {
                int r = brow[np];
                ldmx4(b[np], st + 16384u + (uint32_t)(r * 128 + ((ks ^ (r & 7)) << 4)));
            }
#pragma unroll
            for (int mt = 0; mt < 2; mt++)
#pragma unroll
                for (int nt = 0; nt < 8; nt++)
                    mma16816(acc[mt][nt], a[mt], b[nt >> 1][nt & 1], b[nt >> 1][2 + (nt & 1)]);
        }
        __syncthreads();
        if (c + 2 < NC) load(c + 2, s);
    }

    // epilogue
#pragma unroll
    for (int mt = 0; mt < 2; mt++) {
        int r0 = bi * 128 + wm + mt * 16 + gid;
#pragma unroll
        for (int nt = 0; nt < 8; nt++) {
            int cc = bj * 128 + wn + nt * 8 + 2 * tig;
            TO* p0 = C + (long long)r0 * Nn + cc;
            TO* p1 = p0 + 8 * (long long)Nn;
            if constexpr (sizeof(TO) == 2) {
                *(__half2*)p0 = __floats2half2_rn(acc[mt][nt][0], acc[mt][nt][1]);
                *(__half2*)p1 = __floats2half2_rn(acc[mt][nt][2], acc[mt][nt][3]);
            } else if (ADD) {
                p0[0] += acc[mt][nt][0]; p0[1] += acc[mt][nt][1];
                p1[0] += acc[mt][nt][2]; p1[1] += acc[mt][nt][3];
            } else {
                p0[0] = acc[mt][nt][0]; p0[1] = acc[mt][nt][1];
                p1[0] = acc[mt][nt][2]; p1[1] = acc[mt][nt][3];
            }
        }
    }
}

// ---------------- RMSNorm -> fp16 ----------------
__global__ void rmsnorm_k(const float* __restrict__ x, const float* __restrict__ sc,
                          __half* __restrict__ o)
{
    const int row = blockIdx.x;
    const float* xr = x + (long long)row * DD;
    __half*      orw = o + (long long)row * DD;
    float s = 0.f;
    for (int j = threadIdx.x; j < DD; j += 256) { float v = xr[j]; s += v * v; }
    __shared__ float red[256];
    red[threadIdx.x] = s; __syncthreads();
    for (int t = 128; t > 0; t >>= 1) {
        if (threadIdx.x < t) red[threadIdx.x] += red[threadIdx.x + t];
        __syncthreads();
    }
    float r = rsqrtf(red[0] * (1.0f / DD) + EPSV);
    for (int j = threadIdx.x; j < DD; j += 256) orw[j] = __float2half(xr[j] * r * sc[j]);
}

// ---------------- RoPE + augment (Q and K together) from tmp[M,3D] fp16 ----------------
__global__ void rope_aug2_k(const __half* __restrict__ t,
                            __half* __restrict__ qa, __half* __restrict__ ka)
{
    int idx = blockIdx.x * 256 + threadIdx.x;     // B*S*H*HALF threads
    int d = idx & 63;
    int h = (idx >> 6) & 15;
    int s = (idx >> 10) & 1023;
    int b = idx >> 20;
    const __half* row = t + ((long long)b * SS + s) * (3 * DD);
    float q1 = __half2float(row[h * DHD + d]);
    float q2 = __half2float(row[h * DHD + HALF + d]);
    float k1 = __half2float(row[DD + h * DHD + d]);
    float k2 = __half2float(row[DD + h * DHD + HALF + d]);
    float inv = expf(-(float)d * (9.210340371976184f / 64.0f));
    float ang = (float)s * inv;
    float cs, sn; sincosf(ang, &sn, &cs);
    long long base = (((long long)(b * HH + h)) * SS + s) * KAUG;
    float qo1 = q1 * cs - q2 * sn, qo2 = q1 * sn + q2 * cs;
    float ko1 = k1 * cs - k2 * sn, ko2 = k1 * sn + k2 * cs;
    qa[base + d]              = __float2half(qo1);
    qa[base + HALF + d]       = __float2half(qo2);
    qa[base + DHD + d]        = __float2half(SQLAM * qo1 * qo1);
    qa[base + DHD + HALF + d] = __float2half(SQLAM * qo2 * qo2);
    ka[base + d]              = __float2half(ko1);
    ka[base + HALF + d]       = __float2half(ko2);
    ka[base + DHD + d]        = __float2half(SQLAM * ko1 * ko1);
    ka[base + DHD + HALF + d] = __float2half(SQLAM * ko2 * ko2);
}

// ---------------- V transpose from tmp[M,3D] fp16 -> per-head [DHD,S] ----------------
__global__ void vt_k(const __half* __restrict__ t, __half* __restrict__ out)
{
    __shared__ __half tl[32][33];
    int bh = blockIdx.z;
    int b = bh >> 4, h = bh & 15;
    int s0 = blockIdx.x * 32, d0 = blockIdx.y * 32;
    int tx = threadIdx.x & 31, ty = threadIdx.x >> 5;
    for (int i = ty; i < 32; i += 8) {
        int s = s0 + i, d = d0 + tx;
        tl[i][tx] = t[((long long)(b * SS + s)) * (3 * DD) + 2 * DD + h * DHD + d];
    }
    __syncthreads();
    for (int i = ty; i < 32; i += 8) {
        int d = d0 + i, s = s0 + tx;
        out[((long long)bh * DHD + d) * SS + s] = tl[tx][i];
    }
}

// ---------------- causal softmax: single exp, store unnormalized + 1/sum ----------------
__global__ void softmax_k(const float* __restrict__ sc, __half* __restrict__ ph,
                          float* __restrict__ inv)
{
    long long row = blockIdx.x;
    int i = (int)(row % SS);
    int lim = i | 127;                    // zero-fill out to PV read boundary
    const float* p = sc + row * SS;
    __half* q = ph + row * SS;
    int tid = threadIdx.x;
    __shared__ float red[256];

    float m = -1e30f;
    for (int j = tid; j <= i; j += 256) m = fmaxf(m, p[j] * SCALE);
    red[tid] = m; __syncthreads();
    for (int t = 128; t > 0; t >>= 1) {
        if (tid < t) red[tid] = fmaxf(red[tid], red[tid + t]);
        __syncthreads();
    }
    m = red[0]; __syncthreads();

    float sum = 0.f;
    for (int j = tid; j <= lim; j += 256) {
        if (j <= i) {
            float e = expf(p[j] * SCALE - m);
            q[j] = __float2half(e);
            sum += e;
        } else {
            q[j] = __half(0.f);
        }
    }
    red[tid] = sum; __syncthreads();
    for (int t = 128; t > 0; t >>= 1) {
        if (tid < t) red[tid] += red[tid + t];
        __syncthreads();
    }
    if (tid == 0) inv[row] = 1.f / red[0];
}

// ---------------- normalize + hadamard mix + transpose -> fp16 [M,D] ----------------
__global__ void mix_transpose_k(const float* __restrict__ ao, const float* __restrict__ inv,
                                __half* __restrict__ out)
{
    int idx = blockIdx.x * 256 + threadIdx.x;
    int d  = idx & 127;
    int s  = (idx >> 7) & 1023;
    int bh = idx >> 17;
    int h = bh & 15, b = bh >> 4;
    float iv = inv[(long long)bh * SS + s];
    float v  = ao[idx] * iv;
    float pv = ao[(idx - d) | ((d + 127) & 127)] * iv;
    out[((long long)(b * SS + s)) * DD + h * DHD + d] = __float2half(v * (1.f + HS * pv));
}

// ---------------- fused silu*up + hadamard mix -> fp16 hidden ----------------
__global__ void silu_mix_k(const __half* __restrict__ gu, __half* __restrict__ hh)
{
    int i = blockIdx.x * 256 + threadIdx.x;       // M*F threads
    int m = i >> 13;                               // F = 8192
    int c = i & (FF - 1);
    const __half* row = gu + (long long)m * (2 * FF);
    int pc = (c + FF - 1) & (FF - 1);
    float g  = __half2float(row[c]),  u  = __half2float(row[FF + c]);
    float g2 = __half2float(row[pc]), u2 = __half2float(row[FF + pc]);
    float h  = g  / (1.f + expf(-g))  * u;
    float h2 = g2 / (1.f + expf(-g2)) * u2;
    hh[i] = __float2half(h * (1.f + HS * h2));
}

// ---------------- misc elementwise ----------------
__global__ void copy_k(float* __restrict__ dst, const float* __restrict__ src, int n)
{ int i = blockIdx.x * 256 + threadIdx.x; if (i < n) dst[i] = src[i]; }

// vectorized fp32->fp16 (n divisible by 4)
__global__ void w2h_k(__half* __restrict__ dst, const float* __restrict__ src, int n4)
{
    int i = blockIdx.x * 256 + threadIdx.x;
    if (i < n4) {
        float4 v = ((const float4*)src)[i];
        __half2 lo = __floats2half2_rn(v.x, v.y);
        __half2 hi = __floats2half2_rn(v.z, v.w);
        ((uint2*)dst)[i] = make_uint2(*(uint32_t*)&lo, *(uint32_t*)&hi);
    }
}

__global__ void x2_k(float* __restrict__ cur, const float* __restrict__ h1,
                     const float* __restrict__ x, int n)
{ int i = blockIdx.x * 256 + threadIdx.x; if (i < n) cur[i] = (1.f + BETA) * h1[i] - BETA * x[i]; }

__global__ void final_k(float* __restrict__ out, const float* __restrict__ h1,
                        const float* __restrict__ h2, int n)
{
    int i = blockIdx.x * 256 + threadIdx.x;
    if (i < n) {
        float v = ALPHA * h1[i] + (1.f - ALPHA) * h2[i];
        out[i] = fminf(fmaxf(v, -CLIPV), CLIPV);
    }
}

// ---------------- host orchestration ----------------
#define HSMEM (2*HSTAGE)

static void run_pass(const __half* wqkv, const __half* wo, const __half* wgu, const __half* wd,
                     const float* na, const float* nb,
                     float* cur, __half* xn, __half* tmp,
                     __half* qa, __half* ka, __half* vt, float* ao, float* inv,
                     float* sc, __half* ph, __half* gu, __half* hh)
{
    const int nMD = MM * DD, nMF = MM * FF;

    rmsnorm_k<<<MM, 256>>>(cur, na, xn);

    // fused QKV: [M, 3D](fp16) = xn * wqkv^T
    hgemm<__half,false,false,false><<<dim3(3*DD/128, MM/128, 1), 256, HSMEM>>>(
        xn, wqkv, tmp, DD, 3*DD, 0, 0, 0);
    rope_aug2_k<<<(BB*SS*HH*HALF)/256, 256>>>(tmp, qa, ka);
    vt_k<<<dim3(SS/32, DHD/32, BB*HH), 256>>>(tmp, vt);

    // causal scores: lower-triangle blocks only
    hgemm<float,false,true,false><<<dim3(36, 1, BB*HH), 256, HSMEM>>>(
        qa, ka, sc, KAUG, SS,
        (long long)SS*KAUG, (long long)SS*KAUG, (long long)SS*SS);
    softmax_k<<<BB*HH*SS, 256>>>(sc, ph, inv);
    // PV with causal K truncation (unnormalized probs)
    hgemm<float,false,false,true><<<dim3(1, SS/128, BB*HH), 256, HSMEM>>>(
        ph, vt, ao, SS, DHD,
        (long long)SS*SS, (long long)SS*DHD, (long long)SS*DHD);

    mix_transpose_k<<<nMD/256, 256>>>(ao, inv, xn);
    hgemm<float,true,false,false><<<dim3(DD/128, MM/128, 1), 256, HSMEM>>>(
        xn, wo, cur, DD, DD, 0, 0, 0);

    rmsnorm_k<<<MM, 256>>>(cur, nb, xn);
    // fused gate|up: [M, 2F](fp16)
    hgemm<__half,false,false,false><<<dim3(2*FF/128, MM/128, 1), 256, HSMEM>>>(
        xn, wgu, gu, DD, 2*FF, 0, 0, 0);
    silu_mix_k<<<nMF/256, 256>>>(gu, hh);
    hgemm<float,true,false,false><<<dim3(DD/128, MM/128, 1), 256, HSMEM>>>(
        hh, wd, cur, FF, DD, 0, 0, 0);
}

extern "C" void kernel_launch(void* const* d_in, const int* in_sizes, int n_in,
                              void* d_out, int out_size)
{
    (void)in_sizes; (void)n_in; (void)out_size;
    const float* x   = (const float*)d_in[0];
    const float* Wq0 = (const float*)d_in[1];
    const float* Wk0 = (const float*)d_in[2];
    const float* Wv0 = (const float*)d_in[3];
    const float* Wo0 = (const float*)d_in[4];
    // d_in[5] = gate_w: unused (rotate_half invariance => o2 == o1)
    const float* n1 = (const float*)d_in[6];
    const float* n2 = (const float*)d_in[7];
    const float* n3 = (const float*)d_in[8];
    const float* n4 = (const float*)d_in[9];
    const float* Wg0 = (const float*)d_in[10];
    const float* Wu0 = (const float*)d_in[11];
    const float* Wd0 = (const float*)d_in[12];
    float* out = (float*)d_out;

    cudaFuncSetAttribute(hgemm<__half,false,false,false>, cudaFuncAttributeMaxDynamicSharedMemorySize, HSMEM);
    cudaFuncSetAttribute(hgemm<float,true,false,false>,   cudaFuncAttributeMaxDynamicSharedMemorySize, HSMEM);
    cudaFuncSetAttribute(hgemm<float,false,true,false>,   cudaFuncAttributeMaxDynamicSharedMemorySize, HSMEM);
    cudaFuncSetAttribute(hgemm<float,false,false,true>,   cudaFuncAttributeMaxDynamicSharedMemorySize, HSMEM);

    __half *xn, *tmp, *qa, *ka, *vt, *ph, *gu, *hh, *wqkv, *wo, *wgu, *wd;
    float *cur, *h1, *ao, *inv, *sc;
    cudaGetSymbolAddress((void**)&xn,  g_xn);
    cudaGetSymbolAddress((void**)&tmp, g_tmp);
    cudaGetSymbolAddress((void**)&cur, g_cur);
    cudaGetSymbolAddress((void**)&h1,  g_h1);
    cudaGetSymbolAddress((void**)&qa,  g_qa);
    cudaGetSymbolAddress((void**)&ka,  g_ka);
    cudaGetSymbolAddress((void**)&vt,  g_vt);
    cudaGetSymbolAddress((void**)&ao,  g_ao);
    cudaGetSymbolAddress((void**)&inv, g_inv);
    cudaGetSymbolAddress((void**)&sc,  g_sc);
    cudaGetSymbolAddress((void**)&ph,  g_ph);
    cudaGetSymbolAddress((void**)&gu,  g_gu);
    cudaGetSymbolAddress((void**)&hh,  g_hh);
    cudaGetSymbolAddress((void**)&wqkv,g_wqkv);
    cudaGetSymbolAddress((void**)&wo,  g_wo);
    cudaGetSymbolAddress((void**)&wgu, g_wgu);
    cudaGetSymbolAddress((void**)&wd,  g_wd);

    const int nMD = MM * DD;

    // weights -> fp16 (stacked, vectorized)
    w2h_k<<<(DD*DD/4+255)/256, 256>>>(wqkv,            Wq0, DD*DD/4);
    w2h_k<<<(DD*DD/4+255)/256, 256>>>(wqkv + DD*DD,    Wk0, DD*DD/4);
    w2h_k<<<(DD*DD/4+255)/256, 256>>>(wqkv + 2*DD*DD,  Wv0, DD*DD/4);
    w2h_k<<<(DD*DD/4+255)/256, 256>>>(wo,              Wo0, DD*DD/4);
    w2h_k<<<(FF*DD/4+255)/256, 256>>>(wgu,             Wg0, FF*DD/4);
    w2h_k<<<(FF*DD/4+255)/256, 256>>>(wgu + FF*DD,     Wu0, FF*DD/4);
    w2h_k<<<(FF*DD/4+255)/256, 256>>>(wd,              Wd0, FF*DD/4);

    // pass 1
    copy_k<<<(nMD+255)/256, 256>>>(cur, x, nMD);
    run_pass(wqkv, wo, wgu, wd, n1, n2, cur, xn, tmp, qa, ka, vt, ao, inv, sc, ph, gu, hh);
    copy_k<<<(nMD+255)/256, 256>>>(h1, cur, nMD);

    // x2 = h1 + beta*(h1 - x)
    x2_k<<<(nMD+255)/256, 256>>>(cur, h1, x, nMD);

    // pass 2
    run_pass(wqkv, wo, wgu, wd, n3, n4, cur, xn, tmp, qa, ka, vt, ao, inv, sc, ph, gu, hh);

    // out = clip(alpha*h1 + (1-alpha)*h2)
    final_k<<<(nMD+255)/256, 256>>>(out, h1, cur, nMD);
}